// round 1
// baseline (speedup 1.0000x reference)
#include <cuda_runtime.h>
#include <cuda_bf16.h>
#include <math.h>

// Problem constants
#define BB 2
#define LL 1024
#define NN 512
#define NLAYER 2
#define DI 1024
#define SS 16
#define KC 4
#define RR 32
#define EPS 1e-5f

#define MROWS (BB*LL)   // 2048

// Scratch buffers (static device globals; no allocation at runtime)
__device__ __align__(256) float g_xz  [(size_t)MROWS * 2 * DI]; // 16 MB
__device__ __align__(256) float g_xc  [(size_t)MROWS * DI];     // 8 MB
__device__ __align__(256) float g_xdbl[(size_t)MROWS * 64];     // 512 KB
__device__ __align__(256) float g_dt  [(size_t)MROWS * DI];     // 8 MB
__device__ __align__(256) float g_yg  [(size_t)MROWS * DI];     // 8 MB
__device__ __align__(256) float g_acc [(size_t)MROWS * NN];     // 4 MB
__device__ __align__(256) float g_cur [(size_t)MROWS * NN];     // 4 MB

// ---------------------------------------------------------------------------
// Generic NT SGEMM: C[M,N] (+)= A[M,K] * B[N,K]^T   (both K-major row-major)
// EPI: 0 = store, 1 = add, 2 = atomicAdd (split-K), 3 = softplus(v + bias[c])
// gridDim.z splits K (each z-slice handles K/gridDim.z).
// ---------------------------------------------------------------------------
template<int BM, int BN, int BK, int TM, int TN, int EPI>
__global__ void sgemm_nt(const float* __restrict__ A, const float* __restrict__ Bm,
                         float* __restrict__ C, int M, int N, int Kt,
                         int lda, int ldb, int ldc, const float* __restrict__ bias)
{
    constexpr int TX = BN / TN;
    constexpr int TY = BM / TM;
    constexpr int THREADS = TX * TY;
    __shared__ float As[BK][BM + 4];
    __shared__ float Bs[BK][BN + 4];

    const int tid = threadIdx.x;
    const int tx = tid % TX;
    const int ty = tid / TX;
    const int bm = blockIdx.y * BM;
    const int bn = blockIdx.x * BN;
    const int kslice = Kt / gridDim.z;
    const int kbeg = blockIdx.z * kslice;
    const int kend = kbeg + kslice;

    float acc[TM][TN];
#pragma unroll
    for (int m = 0; m < TM; m++)
#pragma unroll
        for (int n = 0; n < TN; n++) acc[m][n] = 0.f;

    for (int k0 = kbeg; k0 < kend; k0 += BK) {
        // Load A tile (BM x BK) transposed into smem, float4 gmem loads
#pragma unroll
        for (int i = 0; i < BM * BK / 4 / THREADS; i++) {
            int idx = tid + i * THREADS;
            int r = idx / (BK / 4);
            int c4 = idx % (BK / 4);
            float4 v = *(const float4*)&A[(size_t)(bm + r) * lda + k0 + c4 * 4];
            As[c4 * 4 + 0][r] = v.x;
            As[c4 * 4 + 1][r] = v.y;
            As[c4 * 4 + 2][r] = v.z;
            As[c4 * 4 + 3][r] = v.w;
        }
#pragma unroll
        for (int i = 0; i < BN * BK / 4 / THREADS; i++) {
            int idx = tid + i * THREADS;
            int r = idx / (BK / 4);
            int c4 = idx % (BK / 4);
            float4 v = *(const float4*)&Bm[(size_t)(bn + r) * ldb + k0 + c4 * 4];
            Bs[c4 * 4 + 0][r] = v.x;
            Bs[c4 * 4 + 1][r] = v.y;
            Bs[c4 * 4 + 2][r] = v.z;
            Bs[c4 * 4 + 3][r] = v.w;
        }
        __syncthreads();

#pragma unroll
        for (int k = 0; k < BK; k++) {
            float ra[TM], rb[TN];
#pragma unroll
            for (int m = 0; m < TM; m++) ra[m] = As[k][ty * TM + m];
#pragma unroll
            for (int n = 0; n < TN; n++) rb[n] = Bs[k][tx * TN + n];
#pragma unroll
            for (int m = 0; m < TM; m++)
#pragma unroll
                for (int n = 0; n < TN; n++)
                    acc[m][n] = fmaf(ra[m], rb[n], acc[m][n]);
        }
        __syncthreads();
    }

#pragma unroll
    for (int m = 0; m < TM; m++) {
        int r = bm + ty * TM + m;
#pragma unroll
        for (int n = 0; n < TN; n++) {
            int c = bn + tx * TN + n;
            size_t off = (size_t)r * ldc + c;
            float v = acc[m][n];
            if (EPI == 0) {
                C[off] = v;
            } else if (EPI == 1) {
                C[off] += v;
            } else if (EPI == 2) {
                atomicAdd(&C[off], v);
            } else { // softplus(v + bias[c])
                float u = v + bias[c];
                float sp = (u > 0.f) ? (u + log1pf(__expf(-u))) : log1pf(__expf(u));
                C[off] = sp;
            }
        }
    }
}

// ---------------------------------------------------------------------------
// Causal depthwise conv (K=4) + SiLU. Direction-aware.
// Reads xr = first DI columns of xz (row stride 2*DI); writes xc (B,L,DI).
// fwd: uses physical l-3..l ; bwd (reversed sequence): physical l..l+3.
// ---------------------------------------------------------------------------
__global__ void conv_silu_kernel(const float* __restrict__ xz,
                                 const float* __restrict__ cw,
                                 const float* __restrict__ cb,
                                 float* __restrict__ xc, int rev)
{
    int idx = blockIdx.x * blockDim.x + threadIdx.x;
    if (idx >= BB * LL * DI) return;
    int d = idx % DI;
    int l = (idx / DI) % LL;
    int b = idx / (DI * LL);

    float acc = cb[d];
#pragma unroll
    for (int k = 0; k < KC; k++) {
        int lp = rev ? (l + (KC - 1) - k) : (l - (KC - 1) + k);
        if (lp >= 0 && lp < LL) {
            acc = fmaf(cw[d * KC + k], xz[((size_t)(b * LL + lp)) * 2 * DI + d], acc);
        }
    }
    float sig = 1.f / (1.f + __expf(-acc));
    xc[idx] = acc * sig;
}

// ---------------------------------------------------------------------------
// Fused selective scan + C-dot + D skip + SiLU(z) gating.
// Block: 256 threads = 16 chains (half-warp each), chain = d0 + tid/16,
// lane s = tid%16 holds state s. Smem-staged 64-step chunks of dt/xc/z/B/C.
// ---------------------------------------------------------------------------
#define SCH 64   // chunk length
#define SCD 16   // chains per block

__global__ void scan_kernel(const float* __restrict__ dt,
                            const float* __restrict__ xc,
                            const float* __restrict__ xz,
                            const float* __restrict__ xdbl,
                            const float* __restrict__ Alog,
                            const float* __restrict__ Dp,
                            float* __restrict__ yg, int rev)
{
    __shared__ float s_dt[SCH][SCD];
    __shared__ float s_xc[SCH][SCD];
    __shared__ float s_z [SCH][SCD];
    __shared__ float s_B [SCH][SS];
    __shared__ float s_C [SCH][SS];
    __shared__ float s_y [SCH][SCD];

    const int tid = threadIdx.x;
    const int cd = tid >> 4;      // chain within block: 0..15
    const int s  = tid & 15;      // state index
    const int d0 = blockIdx.x * SCD;
    const int b  = blockIdx.y;
    const int d  = d0 + cd;

    const float Aneg = -__expf(Alog[(size_t)d * SS + s]);
    const float Dd = Dp[d];

    float h = 0.f;

    for (int t0 = 0; t0 < LL; t0 += SCH) {
        // Stage dt / xc / z tiles
        for (int idx = tid; idx < SCH * SCD; idx += 256) {
            int j = idx / SCD;
            int dl = idx % SCD;
            int p = rev ? (LL - 1 - (t0 + j)) : (t0 + j);
            size_t row = (size_t)(b * LL + p);
            s_dt[j][dl] = dt[row * DI + d0 + dl];
            s_xc[j][dl] = xc[row * DI + d0 + dl];
            s_z [j][dl] = xz[row * 2 * DI + DI + d0 + dl];
        }
        // Stage B / C tiles (cols 32..63 of x_dbl)
        for (int idx = tid; idx < SCH * 2 * SS; idx += 256) {
            int j = idx / (2 * SS);
            int c = idx % (2 * SS);
            int p = rev ? (LL - 1 - (t0 + j)) : (t0 + j);
            float v = xdbl[(size_t)(b * LL + p) * 64 + RR + c];
            if (c < SS) s_B[j][c] = v; else s_C[j][c - SS] = v;
        }
        __syncthreads();

        // Sequential scan over chunk
        for (int j = 0; j < SCH; j++) {
            float dtv = s_dt[j][cd];
            float xv  = s_xc[j][cd];
            float Bv  = s_B[j][s];
            float Cv  = s_C[j][s];
            float dA  = __expf(dtv * Aneg);
            h = fmaf(dA, h, dtv * xv * Bv);
            float c = h * Cv;
            c += __shfl_xor_sync(0xffffffffu, c, 8);
            c += __shfl_xor_sync(0xffffffffu, c, 4);
            c += __shfl_xor_sync(0xffffffffu, c, 2);
            c += __shfl_xor_sync(0xffffffffu, c, 1);
            if (s == 0) s_y[j][cd] = fmaf(xv, Dd, c);
        }
        __syncthreads();

        // Flush: apply SiLU(z) gate, coalesced writes
        for (int idx = tid; idx < SCH * SCD; idx += 256) {
            int j = idx / SCD;
            int dl = idx % SCD;
            int p = rev ? (LL - 1 - (t0 + j)) : (t0 + j);
            float zv = s_z[j][dl];
            float sig = 1.f / (1.f + __expf(-zv));
            yg[(size_t)(b * LL + p) * DI + d0 + dl] = s_y[j][dl] * (zv * sig);
        }
        __syncthreads();
    }
}

// ---------------------------------------------------------------------------
// Two-pass LayerNorm over last dim (N=512). One block (256 threads) per row.
// ---------------------------------------------------------------------------
__global__ void layernorm_kernel(const float* __restrict__ acc,
                                 const float* __restrict__ g,
                                 const float* __restrict__ bta,
                                 float* __restrict__ out)
{
    __shared__ float red[256];
    int row = blockIdx.x;
    int t = threadIdx.x;
    const float* rp = acc + (size_t)row * NN;

    float v0 = rp[t];
    float v1 = rp[t + 256];

    // mean
    red[t] = v0 + v1;
    __syncthreads();
    for (int o = 128; o > 0; o >>= 1) {
        if (t < o) red[t] += red[t + o];
        __syncthreads();
    }
    float mu = red[0] * (1.f / NN);
    __syncthreads();

    // variance (two-pass)
    float c0 = v0 - mu, c1 = v1 - mu;
    red[t] = c0 * c0 + c1 * c1;
    __syncthreads();
    for (int o = 128; o > 0; o >>= 1) {
        if (t < o) red[t] += red[t + o];
        __syncthreads();
    }
    float inv = rsqrtf(red[0] * (1.f / NN) + EPS);

    float* op = out + (size_t)row * NN;
    op[t]       = c0 * inv * g[t]       + bta[t];
    op[t + 256] = c1 * inv * g[t + 256] + bta[t + 256];
}

__global__ void copy_kernel(float* __restrict__ dst, const float* __restrict__ src, int n4)
{
    int i = blockIdx.x * blockDim.x + threadIdx.x;
    if (i < n4) ((float4*)dst)[i] = ((const float4*)src)[i];
}

__global__ void zero_kernel(float* __restrict__ dst, int n)
{
    int i = blockIdx.x * blockDim.x + threadIdx.x;
    if (i < n) dst[i] = 0.f;
}

// ---------------------------------------------------------------------------
extern "C" void kernel_launch(void* const* d_in, const int* in_sizes, int n_in,
                              void* d_out, int out_size)
{
    const float* x    = (const float*)d_in[0];
    const float* inw  = (const float*)d_in[1];
    const float* cw   = (const float*)d_in[2];
    const float* cb   = (const float*)d_in[3];
    const float* xw   = (const float*)d_in[4];
    const float* dtw  = (const float*)d_in[5];
    const float* dtb  = (const float*)d_in[6];
    const float* Alog = (const float*)d_in[7];
    const float* Dp   = (const float*)d_in[8];
    const float* ow   = (const float*)d_in[9];
    const float* lng  = (const float*)d_in[10];
    const float* lnb  = (const float*)d_in[11];

    float *xz, *xc, *xdbl, *dt, *yg, *acc, *cur;
    cudaGetSymbolAddress((void**)&xz,   g_xz);
    cudaGetSymbolAddress((void**)&xc,   g_xc);
    cudaGetSymbolAddress((void**)&xdbl, g_xdbl);
    cudaGetSymbolAddress((void**)&dt,   g_dt);
    cudaGetSymbolAddress((void**)&yg,   g_yg);
    cudaGetSymbolAddress((void**)&acc,  g_acc);
    cudaGetSymbolAddress((void**)&cur,  g_cur);

    const float* layer_in = x;

    for (int l = 0; l < NLAYER; l++) {
        // acc = layer input (residual)
        copy_kernel<<<(MROWS * NN / 4 + 255) / 256, 256>>>(acc, layer_in, MROWS * NN / 4);

        for (int dir = 0; dir < 2; dir++) {
            int i = 2 * l + dir;

            // in_proj: xz[2048,2048] = layer_in[2048,512] @ W[2048,512]^T
            sgemm_nt<128, 64, 16, 8, 4, 0><<<dim3(2 * DI / 64, MROWS / 128, 1), 256>>>(
                layer_in, inw + (size_t)i * 2 * DI * NN, xz,
                MROWS, 2 * DI, NN, NN, NN, 2 * DI, nullptr);

            // depthwise causal conv + SiLU
            conv_silu_kernel<<<(BB * LL * DI + 255) / 256, 256>>>(
                xz, cw + (size_t)i * DI * KC, cb + (size_t)i * DI, xc, dir);

            // xproj (split-K=8, atomic accumulate): x_dbl[2048,64]
            zero_kernel<<<(MROWS * 64 + 255) / 256, 256>>>(xdbl, MROWS * 64);
            sgemm_nt<64, 64, 16, 4, 4, 2><<<dim3(1, MROWS / 64, 8), 256>>>(
                xc, xw + (size_t)i * 64 * DI, xdbl,
                MROWS, 64, DI, DI, DI, 64, nullptr);

            // dtproj + bias + softplus: dt[2048,1024] (A = first 32 cols of x_dbl)
            sgemm_nt<128, 64, 16, 8, 4, 3><<<dim3(DI / 64, MROWS / 128, 1), 256>>>(
                xdbl, dtw + (size_t)i * DI * RR, dt,
                MROWS, DI, RR, 64, RR, DI, dtb + (size_t)i * DI);

            // fused selective scan + gate
            scan_kernel<<<dim3(DI / SCD, BB), 256>>>(
                dt, xc, xz, xdbl, Alog + (size_t)i * DI * SS, Dp + (size_t)i * DI, yg, dir);

            // out_proj, accumulated into residual
            sgemm_nt<128, 64, 16, 8, 4, 1><<<dim3(NN / 64, MROWS / 128, 1), 256>>>(
                yg, ow + (size_t)i * NN * DI, acc,
                MROWS, NN, DI, DI, DI, NN, nullptr);
        }

        float* lnout = (l == NLAYER - 1) ? (float*)d_out : cur;
        layernorm_kernel<<<MROWS, 256>>>(acc, lng + (size_t)l * NN, lnb + (size_t)l * NN, lnout);
        layer_in = cur;
    }
}

// round 3
// speedup vs baseline: 1.2906x; 1.2906x over previous
#include <cuda_runtime.h>
#include <cuda_bf16.h>
#include <math.h>
#include <stdint.h>

// Problem constants
#define BB 2
#define LL 1024
#define NN 512
#define NLAYER 2
#define DI 1024
#define SSN 16
#define KC 4
#define RR 32
#define EPS 1e-5f
#define MROWS (BB*LL)   // 2048

// Scratch buffers (static device globals; no runtime allocation)
__device__ __align__(256) float g_xz  [(size_t)MROWS * 2 * DI];
__device__ __align__(256) float g_xc  [(size_t)MROWS * DI];
__device__ __align__(256) float g_xdbl[(size_t)MROWS * 64];
__device__ __align__(256) float g_dt  [(size_t)MROWS * DI];
__device__ __align__(256) float g_yg  [(size_t)MROWS * DI];
__device__ __align__(256) float g_acc [(size_t)MROWS * NN];
__device__ __align__(256) float g_cur [(size_t)MROWS * NN];

// ===========================================================================
// HMMA helpers (sm_80+ path; works with plain sm_100 PTX target)
// ===========================================================================
static __device__ __forceinline__ uint32_t smem_u32(const void* p) {
    uint32_t a;
    asm("{ .reg .u64 t; cvta.to.shared.u64 t, %1; cvt.u32.u64 %0, t; }" : "=r"(a) : "l"(p));
    return a;
}

static __device__ __forceinline__ void ldsm4(uint32_t* r, uint32_t addr) {
    asm volatile("ldmatrix.sync.aligned.m8n8.x4.shared.b16 {%0,%1,%2,%3}, [%4];"
        : "=r"(r[0]), "=r"(r[1]), "=r"(r[2]), "=r"(r[3]) : "r"(addr));
}

static __device__ __forceinline__ void mma_bf16(float* c, const uint32_t* a,
                                                uint32_t b0, uint32_t b1) {
    asm volatile(
        "mma.sync.aligned.m16n8k16.row.col.f32.bf16.bf16.f32 "
        "{%0,%1,%2,%3}, {%4,%5,%6,%7}, {%8,%9}, {%0,%1,%2,%3};"
        : "+f"(c[0]), "+f"(c[1]), "+f"(c[2]), "+f"(c[3])
        : "r"(a[0]), "r"(a[1]), "r"(a[2]), "r"(a[3]), "r"(b0), "r"(b1));
}

// ===========================================================================
// bf16x3 NT GEMM on tensor cores: C[M,N] (+)= A[M,K] @ B[N,K]^T, fp32 I/O.
// Block 128x128, 8 warps of 64x32, BK=32. Smem rows padded to 40 bf16 (80 B)
// -> conflict-free ldmatrix. hi/lo split: 3 MMAs per k-step for fp32 accuracy.
// ===========================================================================
#define PAD 40

static __device__ __forceinline__ void split_store(__nv_bfloat16* hi, __nv_bfloat16* lo,
                                                   int off, float4 v) {
    __nv_bfloat162 h01 = __floats2bfloat162_rn(v.x, v.y);
    __nv_bfloat162 h23 = __floats2bfloat162_rn(v.z, v.w);
    float2 f01 = __bfloat1622float2(h01);
    float2 f23 = __bfloat1622float2(h23);
    __nv_bfloat162 l01 = __floats2bfloat162_rn(v.x - f01.x, v.y - f01.y);
    __nv_bfloat162 l23 = __floats2bfloat162_rn(v.z - f23.x, v.w - f23.y);
    *(__nv_bfloat162*)(hi + off)     = h01;
    *(__nv_bfloat162*)(hi + off + 2) = h23;
    *(__nv_bfloat162*)(lo + off)     = l01;
    *(__nv_bfloat162*)(lo + off + 2) = l23;
}

__global__ void __launch_bounds__(256, 2) hgemm_nt(const float* __restrict__ A,
                                                   const float* __restrict__ Bw,
                                                   float* __restrict__ C,
                                                   int K, int lda, int ldb, int ldc, int epi)
{
    __shared__ __align__(16) __nv_bfloat16 sAhi[128 * PAD];
    __shared__ __align__(16) __nv_bfloat16 sAlo[128 * PAD];
    __shared__ __align__(16) __nv_bfloat16 sBhi[128 * PAD];
    __shared__ __align__(16) __nv_bfloat16 sBlo[128 * PAD];

    const int tid = threadIdx.x;
    const int wid = tid >> 5, lane = tid & 31;
    const int wm = wid >> 2, wn = wid & 3;      // 2 x 4 warp grid
    const int bm = blockIdx.y * 128;
    const int bn = blockIdx.x * 128;

    const uint32_t aAhi = smem_u32(sAhi);
    const uint32_t aAlo = smem_u32(sAlo);
    const uint32_t aBhi = smem_u32(sBhi);
    const uint32_t aBlo = smem_u32(sBlo);

    const int lrow   = lane & 15;
    const int lchunk = lane >> 4;

    float acc[4][4][4];
#pragma unroll
    for (int i = 0; i < 4; i++)
#pragma unroll
        for (int j = 0; j < 4; j++)
#pragma unroll
            for (int q = 0; q < 4; q++) acc[i][j][q] = 0.f;

    for (int k0 = 0; k0 < K; k0 += 32) {
        __syncthreads();
        // Load fp32 tiles, split to bf16 hi/lo in smem (128 rows x 32 cols each)
#pragma unroll
        for (int i = 0; i < 4; i++) {
            int idx = tid + i * 256;          // 0..1023 float4 slots
            int r = idx >> 3, c4 = idx & 7;
            float4 va = *(const float4*)(A  + (size_t)(bm + r) * lda + k0 + c4 * 4);
            split_store(sAhi, sAlo, r * PAD + c4 * 4, va);
            float4 vb = *(const float4*)(Bw + (size_t)(bn + r) * ldb + k0 + c4 * 4);
            split_store(sBhi, sBlo, r * PAD + c4 * 4, vb);
        }
        __syncthreads();

#pragma unroll
        for (int ks = 0; ks < 2; ks++) {
            uint32_t ahi[4][4], alo[4][4];
#pragma unroll
            for (int mt = 0; mt < 4; mt++) {
                uint32_t off = (uint32_t)((wm * 64 + mt * 16 + lrow) * PAD
                                          + ks * 16 + lchunk * 8) * 2;
                ldsm4(ahi[mt], aAhi + off);
                ldsm4(alo[mt], aAlo + off);
            }
            uint32_t bhi[2][4], blo[2][4];
#pragma unroll
            for (int np = 0; np < 2; np++) {
                uint32_t off = (uint32_t)((wn * 32 + np * 16 + lrow) * PAD
                                          + ks * 16 + lchunk * 8) * 2;
                ldsm4(bhi[np], aBhi + off);
                ldsm4(blo[np], aBlo + off);
            }
#pragma unroll
            for (int mt = 0; mt < 4; mt++)
#pragma unroll
                for (int np = 0; np < 2; np++)
#pragma unroll
                    for (int sub = 0; sub < 2; sub++) {
                        int nt = np * 2 + sub;
                        mma_bf16(acc[mt][nt], ahi[mt], bhi[np][sub], bhi[np][sub + 2]);
                        mma_bf16(acc[mt][nt], ahi[mt], blo[np][sub], blo[np][sub + 2]);
                        mma_bf16(acc[mt][nt], alo[mt], bhi[np][sub], bhi[np][sub + 2]);
                    }
        }
    }

    // Epilogue: fragment -> gmem (float2 stores)
    const int r0 = lane >> 2;
    const int c0 = (lane & 3) * 2;
#pragma unroll
    for (int mt = 0; mt < 4; mt++) {
#pragma unroll
        for (int nt = 0; nt < 4; nt++) {
            int m = bm + wm * 64 + mt * 16 + r0;
            int n = bn + wn * 32 + nt * 8 + c0;
            float2* p0 = (float2*)&C[(size_t)m * ldc + n];
            float2* p1 = (float2*)&C[(size_t)(m + 8) * ldc + n];
            float* a = acc[mt][nt];
            if (epi) {
                float2 o0 = *p0, o1 = *p1;
                o0.x += a[0]; o0.y += a[1];
                o1.x += a[2]; o1.y += a[3];
                *p0 = o0; *p1 = o1;
            } else {
                *p0 = make_float2(a[0], a[1]);
                *p1 = make_float2(a[2], a[3]);
            }
        }
    }
}

// ===========================================================================
// CUDA-core SGEMM for the small GEMMs (xproj, dtproj)
// EPI: 0 store, 1 add, 2 atomicAdd (split-K), 3 softplus(v + bias[c])
// ===========================================================================
template<int BM, int BN, int BK, int TM, int TN, int EPI>
__global__ void sgemm_nt(const float* __restrict__ A, const float* __restrict__ Bm,
                         float* __restrict__ C, int M, int N, int Kt,
                         int lda, int ldb, int ldc, const float* __restrict__ bias)
{
    constexpr int TX = BN / TN;
    constexpr int TY = BM / TM;
    constexpr int THREADS = TX * TY;
    __shared__ float As[BK][BM + 4];
    __shared__ float Bs[BK][BN + 4];

    const int tid = threadIdx.x;
    const int tx = tid % TX;
    const int ty = tid / TX;
    const int bm = blockIdx.y * BM;
    const int bn = blockIdx.x * BN;
    const int kslice = Kt / gridDim.z;
    const int kbeg = blockIdx.z * kslice;
    const int kend = kbeg + kslice;

    float acc[TM][TN];
#pragma unroll
    for (int m = 0; m < TM; m++)
#pragma unroll
        for (int n = 0; n < TN; n++) acc[m][n] = 0.f;

    for (int k0 = kbeg; k0 < kend; k0 += BK) {
#pragma unroll
        for (int i = 0; i < BM * BK / 4 / THREADS; i++) {
            int idx = tid + i * THREADS;
            int r = idx / (BK / 4);
            int c4 = idx % (BK / 4);
            float4 v = *(const float4*)&A[(size_t)(bm + r) * lda + k0 + c4 * 4];
            As[c4 * 4 + 0][r] = v.x;
            As[c4 * 4 + 1][r] = v.y;
            As[c4 * 4 + 2][r] = v.z;
            As[c4 * 4 + 3][r] = v.w;
        }
#pragma unroll
        for (int i = 0; i < BN * BK / 4 / THREADS; i++) {
            int idx = tid + i * THREADS;
            int r = idx / (BK / 4);
            int c4 = idx % (BK / 4);
            float4 v = *(const float4*)&Bm[(size_t)(bn + r) * ldb + k0 + c4 * 4];
            Bs[c4 * 4 + 0][r] = v.x;
            Bs[c4 * 4 + 1][r] = v.y;
            Bs[c4 * 4 + 2][r] = v.z;
            Bs[c4 * 4 + 3][r] = v.w;
        }
        __syncthreads();

#pragma unroll
        for (int k = 0; k < BK; k++) {
            float ra[TM], rb[TN];
#pragma unroll
            for (int m = 0; m < TM; m++) ra[m] = As[k][ty * TM + m];
#pragma unroll
            for (int n = 0; n < TN; n++) rb[n] = Bs[k][tx * TN + n];
#pragma unroll
            for (int m = 0; m < TM; m++)
#pragma unroll
                for (int n = 0; n < TN; n++)
                    acc[m][n] = fmaf(ra[m], rb[n], acc[m][n]);
        }
        __syncthreads();
    }

#pragma unroll
    for (int m = 0; m < TM; m++) {
        int r = bm + ty * TM + m;
#pragma unroll
        for (int n = 0; n < TN; n++) {
            int c = bn + tx * TN + n;
            size_t off = (size_t)r * ldc + c;
            float v = acc[m][n];
            if (EPI == 0) {
                C[off] = v;
            } else if (EPI == 1) {
                C[off] += v;
            } else if (EPI == 2) {
                atomicAdd(&C[off], v);
            } else {
                float u = v + bias[c];
                float sp = (u > 0.f) ? (u + log1pf(__expf(-u))) : log1pf(__expf(u));
                C[off] = sp;
            }
        }
    }
}

// ===========================================================================
// Causal depthwise conv (K=4) + SiLU (direction-aware)
// ===========================================================================
__global__ void conv_silu_kernel(const float* __restrict__ xz,
                                 const float* __restrict__ cw,
                                 const float* __restrict__ cb,
                                 float* __restrict__ xc, int rev)
{
    int idx = blockIdx.x * blockDim.x + threadIdx.x;
    if (idx >= BB * LL * DI) return;
    int d = idx % DI;
    int l = (idx / DI) % LL;
    int b = idx / (DI * LL);

    float acc = cb[d];
#pragma unroll
    for (int k = 0; k < KC; k++) {
        int lp = rev ? (l + (KC - 1) - k) : (l - (KC - 1) + k);
        if (lp >= 0 && lp < LL) {
            acc = fmaf(cw[d * KC + k], xz[((size_t)(b * LL + lp)) * 2 * DI + d], acc);
        }
    }
    float sig = 1.f / (1.f + __expf(-acc));
    xc[idx] = acc * sig;
}

// ===========================================================================
// Fused selective scan + C-dot + D skip + SiLU(z) gating
// ===========================================================================
#define SCH 64
#define SCD 16

__global__ void scan_kernel(const float* __restrict__ dt,
                            const float* __restrict__ xc,
                            const float* __restrict__ xz,
                            const float* __restrict__ xdbl,
                            const float* __restrict__ Alog,
                            const float* __restrict__ Dp,
                            float* __restrict__ yg, int rev)
{
    __shared__ float s_dt[SCH][SCD];
    __shared__ float s_xc[SCH][SCD];
    __shared__ float s_z [SCH][SCD];
    __shared__ float s_B [SCH][SSN];
    __shared__ float s_C [SCH][SSN];
    __shared__ float s_y [SCH][SCD];

    const int tid = threadIdx.x;
    const int cd = tid >> 4;
    const int s  = tid & 15;
    const int d0 = blockIdx.x * SCD;
    const int b  = blockIdx.y;
    const int d  = d0 + cd;

    const float Aneg = -__expf(Alog[(size_t)d * SSN + s]);
    const float Dd = Dp[d];

    float h = 0.f;

    for (int t0 = 0; t0 < LL; t0 += SCH) {
        for (int idx = tid; idx < SCH * SCD; idx += 256) {
            int j = idx / SCD;
            int dl = idx % SCD;
            int p = rev ? (LL - 1 - (t0 + j)) : (t0 + j);
            size_t row = (size_t)(b * LL + p);
            s_dt[j][dl] = dt[row * DI + d0 + dl];
            s_xc[j][dl] = xc[row * DI + d0 + dl];
            s_z [j][dl] = xz[row * 2 * DI + DI + d0 + dl];
        }
        for (int idx = tid; idx < SCH * 2 * SSN; idx += 256) {
            int j = idx / (2 * SSN);
            int c = idx % (2 * SSN);
            int p = rev ? (LL - 1 - (t0 + j)) : (t0 + j);
            float v = xdbl[(size_t)(b * LL + p) * 64 + RR + c];
            if (c < SSN) s_B[j][c] = v; else s_C[j][c - SSN] = v;
        }
        __syncthreads();

        for (int j = 0; j < SCH; j++) {
            float dtv = s_dt[j][cd];
            float xv  = s_xc[j][cd];
            float Bv  = s_B[j][s];
            float Cv  = s_C[j][s];
            float dA  = __expf(dtv * Aneg);
            h = fmaf(dA, h, dtv * xv * Bv);
            float c = h * Cv;
            c += __shfl_xor_sync(0xffffffffu, c, 8);
            c += __shfl_xor_sync(0xffffffffu, c, 4);
            c += __shfl_xor_sync(0xffffffffu, c, 2);
            c += __shfl_xor_sync(0xffffffffu, c, 1);
            if (s == 0) s_y[j][cd] = fmaf(xv, Dd, c);
        }
        __syncthreads();

        for (int idx = tid; idx < SCH * SCD; idx += 256) {
            int j = idx / SCD;
            int dl = idx % SCD;
            int p = rev ? (LL - 1 - (t0 + j)) : (t0 + j);
            float zv = s_z[j][dl];
            float sig = 1.f / (1.f + __expf(-zv));
            yg[(size_t)(b * LL + p) * DI + d0 + dl] = s_y[j][dl] * (zv * sig);
        }
        __syncthreads();
    }
}

// ===========================================================================
// LayerNorm, copy, zero
// ===========================================================================
__global__ void layernorm_kernel(const float* __restrict__ acc,
                                 const float* __restrict__ g,
                                 const float* __restrict__ bta,
                                 float* __restrict__ out)
{
    __shared__ float red[256];
    int row = blockIdx.x;
    int t = threadIdx.x;
    const float* rp = acc + (size_t)row * NN;

    float v0 = rp[t];
    float v1 = rp[t + 256];

    red[t] = v0 + v1;
    __syncthreads();
    for (int o = 128; o > 0; o >>= 1) {
        if (t < o) red[t] += red[t + o];
        __syncthreads();
    }
    float mu = red[0] * (1.f / NN);
    __syncthreads();

    float c0 = v0 - mu, c1 = v1 - mu;
    red[t] = c0 * c0 + c1 * c1;
    __syncthreads();
    for (int o = 128; o > 0; o >>= 1) {
        if (t < o) red[t] += red[t + o];
        __syncthreads();
    }
    float inv = rsqrtf(red[0] * (1.f / NN) + EPS);

    float* op = out + (size_t)row * NN;
    op[t]       = c0 * inv * g[t]       + bta[t];
    op[t + 256] = c1 * inv * g[t + 256] + bta[t + 256];
}

__global__ void copy_kernel(float* __restrict__ dst, const float* __restrict__ src, int n4)
{
    int i = blockIdx.x * blockDim.x + threadIdx.x;
    if (i < n4) ((float4*)dst)[i] = ((const float4*)src)[i];
}

__global__ void zero_kernel(float* __restrict__ dst, int n)
{
    int i = blockIdx.x * blockDim.x + threadIdx.x;
    if (i < n) dst[i] = 0.f;
}

// ===========================================================================
extern "C" void kernel_launch(void* const* d_in, const int* in_sizes, int n_in,
                              void* d_out, int out_size)
{
    const float* x    = (const float*)d_in[0];
    const float* inw  = (const float*)d_in[1];
    const float* cw   = (const float*)d_in[2];
    const float* cb   = (const float*)d_in[3];
    const float* xw   = (const float*)d_in[4];
    const float* dtw  = (const float*)d_in[5];
    const float* dtb  = (const float*)d_in[6];
    const float* Alog = (const float*)d_in[7];
    const float* Dp   = (const float*)d_in[8];
    const float* ow   = (const float*)d_in[9];
    const float* lng  = (const float*)d_in[10];
    const float* lnb  = (const float*)d_in[11];

    float *xz, *xc, *xdbl, *dt, *yg, *acc, *cur;
    cudaGetSymbolAddress((void**)&xz,   g_xz);
    cudaGetSymbolAddress((void**)&xc,   g_xc);
    cudaGetSymbolAddress((void**)&xdbl, g_xdbl);
    cudaGetSymbolAddress((void**)&dt,   g_dt);
    cudaGetSymbolAddress((void**)&yg,   g_yg);
    cudaGetSymbolAddress((void**)&acc,  g_acc);
    cudaGetSymbolAddress((void**)&cur,  g_cur);

    const float* layer_in = x;

    for (int l = 0; l < NLAYER; l++) {
        copy_kernel<<<(MROWS * NN / 4 + 255) / 256, 256>>>(acc, layer_in, MROWS * NN / 4);

        for (int dir = 0; dir < 2; dir++) {
            int i = 2 * l + dir;

            // in_proj: xz[2048,2048] = layer_in[2048,512] @ W[2048,512]^T (HMMA bf16x3)
            hgemm_nt<<<dim3(2 * DI / 128, MROWS / 128), 256>>>(
                layer_in, inw + (size_t)i * 2 * DI * NN, xz,
                NN, NN, NN, 2 * DI, 0);

            // depthwise causal conv + SiLU
            conv_silu_kernel<<<(BB * LL * DI + 255) / 256, 256>>>(
                xz, cw + (size_t)i * DI * KC, cb + (size_t)i * DI, xc, dir);

            // xproj (split-K=8, atomic accumulate): x_dbl[2048,64]
            zero_kernel<<<(MROWS * 64 + 255) / 256, 256>>>(xdbl, MROWS * 64);
            sgemm_nt<64, 64, 16, 4, 4, 2><<<dim3(1, MROWS / 64, 8), 256>>>(
                xc, xw + (size_t)i * 64 * DI, xdbl,
                MROWS, 64, DI, DI, DI, 64, nullptr);

            // dtproj + bias + softplus: dt[2048,1024]
            sgemm_nt<128, 64, 16, 8, 4, 3><<<dim3(DI / 64, MROWS / 128, 1), 256>>>(
                xdbl, dtw + (size_t)i * DI * RR, dt,
                MROWS, DI, RR, 64, RR, DI, dtb + (size_t)i * DI);

            // fused selective scan + gate
            scan_kernel<<<dim3(DI / SCD, BB), 256>>>(
                dt, xc, xz, xdbl, Alog + (size_t)i * DI * SSN, Dp + (size_t)i * DI, yg, dir);

            // out_proj, accumulated into residual (HMMA bf16x3)
            hgemm_nt<<<dim3(NN / 128, MROWS / 128), 256>>>(
                yg, ow + (size_t)i * NN * DI, acc,
                DI, DI, DI, NN, 1);
        }

        float* lnout = (l == NLAYER - 1) ? (float*)d_out : cur;
        layernorm_kernel<<<MROWS, 256>>>(acc, lng + (size_t)l * NN, lnb + (size_t)l * NN, lnout);
        layer_in = cur;
    }
}

// round 4
// speedup vs baseline: 1.5440x; 1.1964x over previous
#include <cuda_runtime.h>
#include <cuda_fp16.h>
#include <math.h>
#include <stdint.h>

// Problem constants
#define BB 2
#define LL 1024
#define NN 512
#define NLAYER 2
#define DI 1024
#define SSN 16
#define KC 4
#define RR 32
#define EPS 1e-5f
#define MROWS (BB*LL)   // 2048

// Scratch buffers (static device globals; no runtime allocation)
__device__ __align__(256) float g_xz  [(size_t)MROWS * 2 * DI];
__device__ __align__(256) float g_xc  [(size_t)MROWS * DI];
__device__ __align__(256) float g_xdbl[(size_t)MROWS * 64];
__device__ __align__(256) float g_dt  [(size_t)MROWS * DI];
__device__ __align__(256) float g_yg  [(size_t)MROWS * DI];
__device__ __align__(256) float g_acc [(size_t)MROWS * NN];
__device__ __align__(256) float g_cur [(size_t)MROWS * NN];

// ===========================================================================
// HMMA helpers (sm_80+ mma.sync path; valid for plain sm_100 PTX target)
// ===========================================================================
static __device__ __forceinline__ uint32_t smem_u32(const void* p) {
    uint32_t a;
    asm("{ .reg .u64 t; cvta.to.shared.u64 t, %1; cvt.u32.u64 %0, t; }" : "=r"(a) : "l"(p));
    return a;
}

static __device__ __forceinline__ void ldsm4(uint32_t* r, uint32_t addr) {
    asm volatile("ldmatrix.sync.aligned.m8n8.x4.shared.b16 {%0,%1,%2,%3}, [%4];"
        : "=r"(r[0]), "=r"(r[1]), "=r"(r[2]), "=r"(r[3]) : "r"(addr));
}

static __device__ __forceinline__ void mma_f16(float* c, const uint32_t* a,
                                               uint32_t b0, uint32_t b1) {
    asm volatile(
        "mma.sync.aligned.m16n8k16.row.col.f32.f16.f16.f32 "
        "{%0,%1,%2,%3}, {%4,%5,%6,%7}, {%8,%9}, {%0,%1,%2,%3};"
        : "+f"(c[0]), "+f"(c[1]), "+f"(c[2]), "+f"(c[3])
        : "r"(a[0]), "r"(a[1]), "r"(a[2]), "r"(a[3]), "r"(b0), "r"(b1));
}

// ===========================================================================
// fp16x2 NT GEMM on tensor cores: C[M,N] (+)= A[M,K] @ B[N,K]^T, fp32 I/O.
// A split into (hi, lo) fp16 (exact to ~2^-22); B single fp16.
// 2 MMAs per k-step: (ahi + alo) * bhi = a * bhi; only B-rounding error (~2^-13 rms).
// Block 128x128, 8 warps of 64x32, BK=32. PAD=40 (80B rows) -> conflict-free LDSM.
// epi: 0 = store, 1 = add, 2 = atomicAdd (split-K via gridDim.z)
// ===========================================================================
#define PAD 40

__global__ void __launch_bounds__(256, 2) hgemm_nt(const float* __restrict__ A,
                                                   const float* __restrict__ Bw,
                                                   float* __restrict__ C,
                                                   int K, int lda, int ldb, int ldc, int epi)
{
    __shared__ __align__(16) __half sAhi[128 * PAD];
    __shared__ __align__(16) __half sAlo[128 * PAD];
    __shared__ __align__(16) __half sBhi[128 * PAD];

    const int tid = threadIdx.x;
    const int wid = tid >> 5, lane = tid & 31;
    const int wm = wid >> 2, wn = wid & 3;      // 2 x 4 warp grid
    const int bm = blockIdx.y * 128;
    const int bn = blockIdx.x * 128;
    const int kslice = K / gridDim.z;
    const int kbeg = blockIdx.z * kslice;
    const int kend = kbeg + kslice;

    const uint32_t aAhi = smem_u32(sAhi);
    const uint32_t aAlo = smem_u32(sAlo);
    const uint32_t aBhi = smem_u32(sBhi);

    const int lrow   = lane & 15;
    const int lchunk = lane >> 4;

    float acc[4][4][4];
#pragma unroll
    for (int i = 0; i < 4; i++)
#pragma unroll
        for (int j = 0; j < 4; j++)
#pragma unroll
            for (int q = 0; q < 4; q++) acc[i][j][q] = 0.f;

    for (int k0 = kbeg; k0 < kend; k0 += 32) {
        __syncthreads();
        // A: fp32 -> (hi, lo) fp16 split; B: fp32 -> fp16
#pragma unroll
        for (int i = 0; i < 4; i++) {
            int idx = tid + i * 256;          // 0..1023 float4 slots
            int r = idx >> 3, c4 = idx & 7;
            int off = r * PAD + c4 * 4;
            float4 va = *(const float4*)(A + (size_t)(bm + r) * lda + k0 + c4 * 4);
            __half2 h01 = __floats2half2_rn(va.x, va.y);
            __half2 h23 = __floats2half2_rn(va.z, va.w);
            float2 f01 = __half22float2(h01);
            float2 f23 = __half22float2(h23);
            __half2 l01 = __floats2half2_rn(va.x - f01.x, va.y - f01.y);
            __half2 l23 = __floats2half2_rn(va.z - f23.x, va.w - f23.y);
            *(__half2*)(sAhi + off)     = h01;
            *(__half2*)(sAhi + off + 2) = h23;
            *(__half2*)(sAlo + off)     = l01;
            *(__half2*)(sAlo + off + 2) = l23;
            float4 vb = *(const float4*)(Bw + (size_t)(bn + r) * ldb + k0 + c4 * 4);
            *(__half2*)(sBhi + off)     = __floats2half2_rn(vb.x, vb.y);
            *(__half2*)(sBhi + off + 2) = __floats2half2_rn(vb.z, vb.w);
        }
        __syncthreads();

#pragma unroll
        for (int ks = 0; ks < 2; ks++) {
            uint32_t ahi[4][4], alo[4][4];
#pragma unroll
            for (int mt = 0; mt < 4; mt++) {
                uint32_t off = (uint32_t)((wm * 64 + mt * 16 + lrow) * PAD
                                          + ks * 16 + lchunk * 8) * 2;
                ldsm4(ahi[mt], aAhi + off);
                ldsm4(alo[mt], aAlo + off);
            }
            uint32_t bh[2][4];
#pragma unroll
            for (int np = 0; np < 2; np++) {
                uint32_t off = (uint32_t)((wn * 32 + np * 16 + lrow) * PAD
                                          + ks * 16 + lchunk * 8) * 2;
                ldsm4(bh[np], aBhi + off);
            }
#pragma unroll
            for (int mt = 0; mt < 4; mt++)
#pragma unroll
                for (int np = 0; np < 2; np++)
#pragma unroll
                    for (int sub = 0; sub < 2; sub++) {
                        int nt = np * 2 + sub;
                        mma_f16(acc[mt][nt], ahi[mt], bh[np][sub], bh[np][sub + 2]);
                        mma_f16(acc[mt][nt], alo[mt], bh[np][sub], bh[np][sub + 2]);
                    }
        }
    }

    // Epilogue: fragment -> gmem
    const int r0 = lane >> 2;
    const int c0 = (lane & 3) * 2;
#pragma unroll
    for (int mt = 0; mt < 4; mt++) {
#pragma unroll
        for (int nt = 0; nt < 4; nt++) {
            int m = bm + wm * 64 + mt * 16 + r0;
            int n = bn + wn * 32 + nt * 8 + c0;
            float* p0 = &C[(size_t)m * ldc + n];
            float* p1 = &C[(size_t)(m + 8) * ldc + n];
            float* a = acc[mt][nt];
            if (epi == 0) {
                *(float2*)p0 = make_float2(a[0], a[1]);
                *(float2*)p1 = make_float2(a[2], a[3]);
            } else if (epi == 1) {
                float2 o0 = *(float2*)p0, o1 = *(float2*)p1;
                o0.x += a[0]; o0.y += a[1];
                o1.x += a[2]; o1.y += a[3];
                *(float2*)p0 = o0; *(float2*)p1 = o1;
            } else {
                atomicAdd(p0, a[0]); atomicAdd(p0 + 1, a[1]);
                atomicAdd(p1, a[2]); atomicAdd(p1 + 1, a[3]);
            }
        }
    }
}

// ===========================================================================
// CUDA-core SGEMM for the small GEMMs (xproj, dtproj)
// EPI: 0 store, 1 add, 2 atomicAdd (split-K), 3 softplus(v + bias[c])
// ===========================================================================
template<int BM, int BN, int BK, int TM, int TN, int EPI>
__global__ void sgemm_nt(const float* __restrict__ A, const float* __restrict__ Bm,
                         float* __restrict__ C, int M, int N, int Kt,
                         int lda, int ldb, int ldc, const float* __restrict__ bias)
{
    constexpr int TX = BN / TN;
    constexpr int TY = BM / TM;
    constexpr int THREADS = TX * TY;
    __shared__ float As[BK][BM + 4];
    __shared__ float Bs[BK][BN + 4];

    const int tid = threadIdx.x;
    const int tx = tid % TX;
    const int ty = tid / TX;
    const int bm = blockIdx.y * BM;
    const int bn = blockIdx.x * BN;
    const int kslice = Kt / gridDim.z;
    const int kbeg = blockIdx.z * kslice;
    const int kend = kbeg + kslice;

    float acc[TM][TN];
#pragma unroll
    for (int m = 0; m < TM; m++)
#pragma unroll
        for (int n = 0; n < TN; n++) acc[m][n] = 0.f;

    for (int k0 = kbeg; k0 < kend; k0 += BK) {
#pragma unroll
        for (int i = 0; i < BM * BK / 4 / THREADS; i++) {
            int idx = tid + i * THREADS;
            int r = idx / (BK / 4);
            int c4 = idx % (BK / 4);
            float4 v = *(const float4*)&A[(size_t)(bm + r) * lda + k0 + c4 * 4];
            As[c4 * 4 + 0][r] = v.x;
            As[c4 * 4 + 1][r] = v.y;
            As[c4 * 4 + 2][r] = v.z;
            As[c4 * 4 + 3][r] = v.w;
        }
#pragma unroll
        for (int i = 0; i < BN * BK / 4 / THREADS; i++) {
            int idx = tid + i * THREADS;
            int r = idx / (BK / 4);
            int c4 = idx % (BK / 4);
            float4 v = *(const float4*)&Bm[(size_t)(bn + r) * ldb + k0 + c4 * 4];
            Bs[c4 * 4 + 0][r] = v.x;
            Bs[c4 * 4 + 1][r] = v.y;
            Bs[c4 * 4 + 2][r] = v.z;
            Bs[c4 * 4 + 3][r] = v.w;
        }
        __syncthreads();

#pragma unroll
        for (int k = 0; k < BK; k++) {
            float ra[TM], rb[TN];
#pragma unroll
            for (int m = 0; m < TM; m++) ra[m] = As[k][ty * TM + m];
#pragma unroll
            for (int n = 0; n < TN; n++) rb[n] = Bs[k][tx * TN + n];
#pragma unroll
            for (int m = 0; m < TM; m++)
#pragma unroll
                for (int n = 0; n < TN; n++)
                    acc[m][n] = fmaf(ra[m], rb[n], acc[m][n]);
        }
        __syncthreads();
    }

#pragma unroll
    for (int m = 0; m < TM; m++) {
        int r = bm + ty * TM + m;
#pragma unroll
        for (int n = 0; n < TN; n++) {
            int c = bn + tx * TN + n;
            size_t off = (size_t)r * ldc + c;
            float v = acc[m][n];
            if (EPI == 0) {
                C[off] = v;
            } else if (EPI == 1) {
                C[off] += v;
            } else if (EPI == 2) {
                atomicAdd(&C[off], v);
            } else {
                float u = v + bias[c];
                float sp = (u > 0.f) ? (u + log1pf(__expf(-u))) : log1pf(__expf(u));
                C[off] = sp;
            }
        }
    }
}

// ===========================================================================
// Causal depthwise conv (K=4) + SiLU (direction-aware)
// ===========================================================================
__global__ void conv_silu_kernel(const float* __restrict__ xz,
                                 const float* __restrict__ cw,
                                 const float* __restrict__ cb,
                                 float* __restrict__ xc, int rev)
{
    int idx = blockIdx.x * blockDim.x + threadIdx.x;
    if (idx >= BB * LL * DI) return;
    int d = idx % DI;
    int l = (idx / DI) % LL;
    int b = idx / (DI * LL);

    float acc = cb[d];
#pragma unroll
    for (int k = 0; k < KC; k++) {
        int lp = rev ? (l + (KC - 1) - k) : (l - (KC - 1) + k);
        if (lp >= 0 && lp < LL) {
            acc = fmaf(cw[d * KC + k], xz[((size_t)(b * LL + lp)) * 2 * DI + d], acc);
        }
    }
    float sig = 1.f / (1.f + __expf(-acc));
    xc[idx] = acc * sig;
}

// ===========================================================================
// Fused selective scan + C-dot + D skip + SiLU(z) gating
// ===========================================================================
#define SCH 64
#define SCD 16

__global__ void scan_kernel(const float* __restrict__ dt,
                            const float* __restrict__ xc,
                            const float* __restrict__ xz,
                            const float* __restrict__ xdbl,
                            const float* __restrict__ Alog,
                            const float* __restrict__ Dp,
                            float* __restrict__ yg, int rev)
{
    __shared__ float s_dt[SCH][SCD];
    __shared__ float s_xc[SCH][SCD];
    __shared__ float s_z [SCH][SCD];
    __shared__ float s_B [SCH][SSN];
    __shared__ float s_C [SCH][SSN];
    __shared__ float s_y [SCH][SCD];

    const int tid = threadIdx.x;
    const int cd = tid >> 4;
    const int s  = tid & 15;
    const int d0 = blockIdx.x * SCD;
    const int b  = blockIdx.y;
    const int d  = d0 + cd;

    const float Aneg = -__expf(Alog[(size_t)d * SSN + s]);
    const float Dd = Dp[d];

    float h = 0.f;

    for (int t0 = 0; t0 < LL; t0 += SCH) {
        for (int idx = tid; idx < SCH * SCD; idx += 256) {
            int j = idx / SCD;
            int dl = idx % SCD;
            int p = rev ? (LL - 1 - (t0 + j)) : (t0 + j);
            size_t row = (size_t)(b * LL + p);
            s_dt[j][dl] = dt[row * DI + d0 + dl];
            s_xc[j][dl] = xc[row * DI + d0 + dl];
            s_z [j][dl] = xz[row * 2 * DI + DI + d0 + dl];
        }
        for (int idx = tid; idx < SCH * 2 * SSN; idx += 256) {
            int j = idx / (2 * SSN);
            int c = idx % (2 * SSN);
            int p = rev ? (LL - 1 - (t0 + j)) : (t0 + j);
            float v = xdbl[(size_t)(b * LL + p) * 64 + RR + c];
            if (c < SSN) s_B[j][c] = v; else s_C[j][c - SSN] = v;
        }
        __syncthreads();

        for (int j = 0; j < SCH; j++) {
            float dtv = s_dt[j][cd];
            float xv  = s_xc[j][cd];
            float Bv  = s_B[j][s];
            float Cv  = s_C[j][s];
            float dA  = __expf(dtv * Aneg);
            h = fmaf(dA, h, dtv * xv * Bv);
            float c = h * Cv;
            c += __shfl_xor_sync(0xffffffffu, c, 8);
            c += __shfl_xor_sync(0xffffffffu, c, 4);
            c += __shfl_xor_sync(0xffffffffu, c, 2);
            c += __shfl_xor_sync(0xffffffffu, c, 1);
            if (s == 0) s_y[j][cd] = fmaf(xv, Dd, c);
        }
        __syncthreads();

        for (int idx = tid; idx < SCH * SCD; idx += 256) {
            int j = idx / SCD;
            int dl = idx % SCD;
            int p = rev ? (LL - 1 - (t0 + j)) : (t0 + j);
            float zv = s_z[j][dl];
            float sig = 1.f / (1.f + __expf(-zv));
            yg[(size_t)(b * LL + p) * DI + d0 + dl] = s_y[j][dl] * (zv * sig);
        }
        __syncthreads();
    }
}

// ===========================================================================
// LayerNorm, copy, zero
// ===========================================================================
__global__ void layernorm_kernel(const float* __restrict__ acc,
                                 const float* __restrict__ g,
                                 const float* __restrict__ bta,
                                 float* __restrict__ out)
{
    __shared__ float red[256];
    int row = blockIdx.x;
    int t = threadIdx.x;
    const float* rp = acc + (size_t)row * NN;

    float v0 = rp[t];
    float v1 = rp[t + 256];

    red[t] = v0 + v1;
    __syncthreads();
    for (int o = 128; o > 0; o >>= 1) {
        if (t < o) red[t] += red[t + o];
        __syncthreads();
    }
    float mu = red[0] * (1.f / NN);
    __syncthreads();

    float c0 = v0 - mu, c1 = v1 - mu;
    red[t] = c0 * c0 + c1 * c1;
    __syncthreads();
    for (int o = 128; o > 0; o >>= 1) {
        if (t < o) red[t] += red[t + o];
        __syncthreads();
    }
    float inv = rsqrtf(red[0] * (1.f / NN) + EPS);

    float* op = out + (size_t)row * NN;
    op[t]       = c0 * inv * g[t]       + bta[t];
    op[t + 256] = c1 * inv * g[t + 256] + bta[t + 256];
}

__global__ void copy_kernel(float* __restrict__ dst, const float* __restrict__ src, int n4)
{
    int i = blockIdx.x * blockDim.x + threadIdx.x;
    if (i < n4) ((float4*)dst)[i] = ((const float4*)src)[i];
}

__global__ void zero_kernel(float* __restrict__ dst, int n)
{
    int i = blockIdx.x * blockDim.x + threadIdx.x;
    if (i < n) dst[i] = 0.f;
}

// ===========================================================================
extern "C" void kernel_launch(void* const* d_in, const int* in_sizes, int n_in,
                              void* d_out, int out_size)
{
    const float* x    = (const float*)d_in[0];
    const float* inw  = (const float*)d_in[1];
    const float* cw   = (const float*)d_in[2];
    const float* cb   = (const float*)d_in[3];
    const float* xw   = (const float*)d_in[4];
    const float* dtw  = (const float*)d_in[5];
    const float* dtb  = (const float*)d_in[6];
    const float* Alog = (const float*)d_in[7];
    const float* Dp   = (const float*)d_in[8];
    const float* ow   = (const float*)d_in[9];
    const float* lng  = (const float*)d_in[10];
    const float* lnb  = (const float*)d_in[11];

    float *xz, *xc, *xdbl, *dt, *yg, *acc, *cur;
    cudaGetSymbolAddress((void**)&xz,   g_xz);
    cudaGetSymbolAddress((void**)&xc,   g_xc);
    cudaGetSymbolAddress((void**)&xdbl, g_xdbl);
    cudaGetSymbolAddress((void**)&dt,   g_dt);
    cudaGetSymbolAddress((void**)&yg,   g_yg);
    cudaGetSymbolAddress((void**)&acc,  g_acc);
    cudaGetSymbolAddress((void**)&cur,  g_cur);

    const float* layer_in = x;

    for (int l = 0; l < NLAYER; l++) {
        copy_kernel<<<(MROWS * NN / 4 + 255) / 256, 256>>>(acc, layer_in, MROWS * NN / 4);

        for (int dir = 0; dir < 2; dir++) {
            int i = 2 * l + dir;

            // in_proj: xz[2048,2048] = layer_in[2048,512] @ W[2048,512]^T (fp16x2 HMMA)
            hgemm_nt<<<dim3(2 * DI / 128, MROWS / 128, 1), 256>>>(
                layer_in, inw + (size_t)i * 2 * DI * NN, xz,
                NN, NN, NN, 2 * DI, 0);

            // depthwise causal conv + SiLU
            conv_silu_kernel<<<(BB * LL * DI + 255) / 256, 256>>>(
                xz, cw + (size_t)i * DI * KC, cb + (size_t)i * DI, xc, dir);

            // xproj (split-K=8, atomic accumulate): x_dbl[2048,64]
            zero_kernel<<<(MROWS * 64 + 255) / 256, 256>>>(xdbl, MROWS * 64);
            sgemm_nt<64, 64, 16, 4, 4, 2><<<dim3(1, MROWS / 64, 8), 256>>>(
                xc, xw + (size_t)i * 64 * DI, xdbl,
                MROWS, 64, DI, DI, DI, 64, nullptr);

            // dtproj + bias + softplus: dt[2048,1024]
            sgemm_nt<128, 64, 16, 8, 4, 3><<<dim3(DI / 64, MROWS / 128, 1), 256>>>(
                xdbl, dtw + (size_t)i * DI * RR, dt,
                MROWS, DI, RR, 64, RR, DI, dtb + (size_t)i * DI);

            // fused selective scan + gate
            scan_kernel<<<dim3(DI / SCD, BB), 256>>>(
                dt, xc, xz, xdbl, Alog + (size_t)i * DI * SSN, Dp + (size_t)i * DI, yg, dir);

            // out_proj, split-K=2 atomic accumulate into residual (fp16x2 HMMA)
            hgemm_nt<<<dim3(NN / 128, MROWS / 128, 2), 256>>>(
                yg, ow + (size_t)i * NN * DI, acc,
                DI, DI, DI, NN, 2);
        }

        float* lnout = (l == NLAYER - 1) ? (float*)d_out : cur;
        layernorm_kernel<<<MROWS, 256>>>(acc, lng + (size_t)l * NN, lnb + (size_t)l * NN, lnout);
        layer_in = cur;
    }
}

// round 5
// speedup vs baseline: 2.2163x; 1.4354x over previous
#include <cuda_runtime.h>
#include <cuda_fp16.h>
#include <math.h>
#include <stdint.h>

// Problem constants
#define BB 2
#define LL 1024
#define NN 512
#define NLAYER 2
#define DI 1024
#define SSN 16
#define KC 4
#define RR 32
#define EPS 1e-5f
#define MROWS (BB*LL)   // 2048

// Scratch buffers (static device globals; no runtime allocation)
__device__ __align__(256) float g_xz  [(size_t)MROWS * 2 * DI];
__device__ __align__(256) float g_xc  [(size_t)MROWS * DI];
__device__ __align__(256) float g_xdbl[(size_t)MROWS * 64];
__device__ __align__(256) float g_dt  [(size_t)MROWS * DI];
__device__ __align__(256) float g_yg  [(size_t)MROWS * DI];
__device__ __align__(256) float g_acc [(size_t)MROWS * NN];
__device__ __align__(256) float g_cur [(size_t)MROWS * NN];

// ===========================================================================
// HMMA helpers (sm_80+ mma.sync path; valid for plain sm_100 PTX target)
// ===========================================================================
static __device__ __forceinline__ uint32_t smem_u32(const void* p) {
    uint32_t a;
    asm("{ .reg .u64 t; cvta.to.shared.u64 t, %1; cvt.u32.u64 %0, t; }" : "=r"(a) : "l"(p));
    return a;
}

static __device__ __forceinline__ void ldsm4(uint32_t* r, uint32_t addr) {
    asm volatile("ldmatrix.sync.aligned.m8n8.x4.shared.b16 {%0,%1,%2,%3}, [%4];"
        : "=r"(r[0]), "=r"(r[1]), "=r"(r[2]), "=r"(r[3]) : "r"(addr));
}

static __device__ __forceinline__ void mma_f16(float* c, const uint32_t* a,
                                               uint32_t b0, uint32_t b1) {
    asm volatile(
        "mma.sync.aligned.m16n8k16.row.col.f32.f16.f16.f32 "
        "{%0,%1,%2,%3}, {%4,%5,%6,%7}, {%8,%9}, {%0,%1,%2,%3};"
        : "+f"(c[0]), "+f"(c[1]), "+f"(c[2]), "+f"(c[3])
        : "r"(a[0]), "r"(a[1]), "r"(a[2]), "r"(a[3]), "r"(b0), "r"(b1));
}

// ===========================================================================
// fp16x2 NT GEMM on tensor cores: C[M,N] (+)= A[M,K] @ B[N,K]^T, fp32 I/O.
// A split into (hi, lo) fp16 (exact to ~2^-22); B single fp16.
// 2 MMAs per k-step. Block 128x128, 8 warps of 64x32, BK=32, PAD=40.
// epi: 0 = store, 1 = add, 2 = atomicAdd (split-K via gridDim.z)
// ===========================================================================
#define PAD 40

__global__ void __launch_bounds__(256, 2) hgemm_nt(const float* __restrict__ A,
                                                   const float* __restrict__ Bw,
                                                   float* __restrict__ C,
                                                   int K, int lda, int ldb, int ldc, int epi)
{
    __shared__ __align__(16) __half sAhi[128 * PAD];
    __shared__ __align__(16) __half sAlo[128 * PAD];
    __shared__ __align__(16) __half sBhi[128 * PAD];

    const int tid = threadIdx.x;
    const int wid = tid >> 5, lane = tid & 31;
    const int wm = wid >> 2, wn = wid & 3;      // 2 x 4 warp grid
    const int bm = blockIdx.y * 128;
    const int bn = blockIdx.x * 128;
    const int kslice = K / gridDim.z;
    const int kbeg = blockIdx.z * kslice;
    const int kend = kbeg + kslice;

    const uint32_t aAhi = smem_u32(sAhi);
    const uint32_t aAlo = smem_u32(sAlo);
    const uint32_t aBhi = smem_u32(sBhi);

    const int lrow   = lane & 15;
    const int lchunk = lane >> 4;

    float acc[4][4][4];
#pragma unroll
    for (int i = 0; i < 4; i++)
#pragma unroll
        for (int j = 0; j < 4; j++)
#pragma unroll
            for (int q = 0; q < 4; q++) acc[i][j][q] = 0.f;

    for (int k0 = kbeg; k0 < kend; k0 += 32) {
        __syncthreads();
        // A: fp32 -> (hi, lo) fp16 split; B: fp32 -> fp16
#pragma unroll
        for (int i = 0; i < 4; i++) {
            int idx = tid + i * 256;          // 0..1023 float4 slots
            int r = idx >> 3, c4 = idx & 7;
            int off = r * PAD + c4 * 4;
            float4 va = *(const float4*)(A + (size_t)(bm + r) * lda + k0 + c4 * 4);
            __half2 h01 = __floats2half2_rn(va.x, va.y);
            __half2 h23 = __floats2half2_rn(va.z, va.w);
            float2 f01 = __half22float2(h01);
            float2 f23 = __half22float2(h23);
            __half2 l01 = __floats2half2_rn(va.x - f01.x, va.y - f01.y);
            __half2 l23 = __floats2half2_rn(va.z - f23.x, va.w - f23.y);
            *(__half2*)(sAhi + off)     = h01;
            *(__half2*)(sAhi + off + 2) = h23;
            *(__half2*)(sAlo + off)     = l01;
            *(__half2*)(sAlo + off + 2) = l23;
            float4 vb = *(const float4*)(Bw + (size_t)(bn + r) * ldb + k0 + c4 * 4);
            *(__half2*)(sBhi + off)     = __floats2half2_rn(vb.x, vb.y);
            *(__half2*)(sBhi + off + 2) = __floats2half2_rn(vb.z, vb.w);
        }
        __syncthreads();

#pragma unroll
        for (int ks = 0; ks < 2; ks++) {
            uint32_t ahi[4][4], alo[4][4];
#pragma unroll
            for (int mt = 0; mt < 4; mt++) {
                uint32_t off = (uint32_t)((wm * 64 + mt * 16 + lrow) * PAD
                                          + ks * 16 + lchunk * 8) * 2;
                ldsm4(ahi[mt], aAhi + off);
                ldsm4(alo[mt], aAlo + off);
            }
            uint32_t bh[2][4];
#pragma unroll
            for (int np = 0; np < 2; np++) {
                uint32_t off = (uint32_t)((wn * 32 + np * 16 + lrow) * PAD
                                          + ks * 16 + lchunk * 8) * 2;
                ldsm4(bh[np], aBhi + off);
            }
#pragma unroll
            for (int mt = 0; mt < 4; mt++)
#pragma unroll
                for (int np = 0; np < 2; np++)
#pragma unroll
                    for (int sub = 0; sub < 2; sub++) {
                        int nt = np * 2 + sub;
                        mma_f16(acc[mt][nt], ahi[mt], bh[np][sub], bh[np][sub + 2]);
                        mma_f16(acc[mt][nt], alo[mt], bh[np][sub], bh[np][sub + 2]);
                    }
        }
    }

    // Epilogue: fragment -> gmem
    const int r0 = lane >> 2;
    const int c0 = (lane & 3) * 2;
#pragma unroll
    for (int mt = 0; mt < 4; mt++) {
#pragma unroll
        for (int nt = 0; nt < 4; nt++) {
            int m = bm + wm * 64 + mt * 16 + r0;
            int n = bn + wn * 32 + nt * 8 + c0;
            float* p0 = &C[(size_t)m * ldc + n];
            float* p1 = &C[(size_t)(m + 8) * ldc + n];
            float* a = acc[mt][nt];
            if (epi == 0) {
                *(float2*)p0 = make_float2(a[0], a[1]);
                *(float2*)p1 = make_float2(a[2], a[3]);
            } else if (epi == 1) {
                float2 o0 = *(float2*)p0, o1 = *(float2*)p1;
                o0.x += a[0]; o0.y += a[1];
                o1.x += a[2]; o1.y += a[3];
                *(float2*)p0 = o0; *(float2*)p1 = o1;
            } else {
                atomicAdd(p0, a[0]); atomicAdd(p0 + 1, a[1]);
                atomicAdd(p1, a[2]); atomicAdd(p1 + 1, a[3]);
            }
        }
    }
}

// ===========================================================================
// CUDA-core SGEMM for the small GEMMs (xproj, dtproj)
// EPI: 0 store, 1 add, 2 atomicAdd (split-K), 3 softplus(v + bias[c])
// ===========================================================================
template<int BM, int BN, int BK, int TM, int TN, int EPI>
__global__ void sgemm_nt(const float* __restrict__ A, const float* __restrict__ Bm,
                         float* __restrict__ C, int M, int N, int Kt,
                         int lda, int ldb, int ldc, const float* __restrict__ bias)
{
    constexpr int TX = BN / TN;
    constexpr int TY = BM / TM;
    constexpr int THREADS = TX * TY;
    __shared__ float As[BK][BM + 4];
    __shared__ float Bs[BK][BN + 4];

    const int tid = threadIdx.x;
    const int tx = tid % TX;
    const int ty = tid / TX;
    const int bm = blockIdx.y * BM;
    const int bn = blockIdx.x * BN;
    const int kslice = Kt / gridDim.z;
    const int kbeg = blockIdx.z * kslice;
    const int kend = kbeg + kslice;

    float acc[TM][TN];
#pragma unroll
    for (int m = 0; m < TM; m++)
#pragma unroll
        for (int n = 0; n < TN; n++) acc[m][n] = 0.f;

    for (int k0 = kbeg; k0 < kend; k0 += BK) {
#pragma unroll
        for (int i = 0; i < BM * BK / 4 / THREADS; i++) {
            int idx = tid + i * THREADS;
            int r = idx / (BK / 4);
            int c4 = idx % (BK / 4);
            float4 v = *(const float4*)&A[(size_t)(bm + r) * lda + k0 + c4 * 4];
            As[c4 * 4 + 0][r] = v.x;
            As[c4 * 4 + 1][r] = v.y;
            As[c4 * 4 + 2][r] = v.z;
            As[c4 * 4 + 3][r] = v.w;
        }
#pragma unroll
        for (int i = 0; i < BN * BK / 4 / THREADS; i++) {
            int idx = tid + i * THREADS;
            int r = idx / (BK / 4);
            int c4 = idx % (BK / 4);
            float4 v = *(const float4*)&Bm[(size_t)(bn + r) * ldb + k0 + c4 * 4];
            Bs[c4 * 4 + 0][r] = v.x;
            Bs[c4 * 4 + 1][r] = v.y;
            Bs[c4 * 4 + 2][r] = v.z;
            Bs[c4 * 4 + 3][r] = v.w;
        }
        __syncthreads();

#pragma unroll
        for (int k = 0; k < BK; k++) {
            float ra[TM], rb[TN];
#pragma unroll
            for (int m = 0; m < TM; m++) ra[m] = As[k][ty * TM + m];
#pragma unroll
            for (int n = 0; n < TN; n++) rb[n] = Bs[k][tx * TN + n];
#pragma unroll
            for (int m = 0; m < TM; m++)
#pragma unroll
                for (int n = 0; n < TN; n++)
                    acc[m][n] = fmaf(ra[m], rb[n], acc[m][n]);
        }
        __syncthreads();
    }

#pragma unroll
    for (int m = 0; m < TM; m++) {
        int r = bm + ty * TM + m;
#pragma unroll
        for (int n = 0; n < TN; n++) {
            int c = bn + tx * TN + n;
            size_t off = (size_t)r * ldc + c;
            float v = acc[m][n];
            if (EPI == 0) {
                C[off] = v;
            } else if (EPI == 1) {
                C[off] += v;
            } else if (EPI == 2) {
                atomicAdd(&C[off], v);
            } else {
                float u = v + bias[c];
                float sp = (u > 0.f) ? (u + log1pf(__expf(-u))) : log1pf(__expf(u));
                C[off] = sp;
            }
        }
    }
}

// ===========================================================================
// Causal depthwise conv (K=4) + SiLU, float4-vectorized over d.
// ===========================================================================
__global__ void conv_silu_kernel(const float* __restrict__ xz,
                                 const float* __restrict__ cw,
                                 const float* __restrict__ cb,
                                 float* __restrict__ xc, int rev)
{
    int idx = blockIdx.x * blockDim.x + threadIdx.x;   // over B*L*DI/4
    if (idx >= BB * LL * DI / 4) return;
    int d4 = (idx % (DI / 4)) * 4;
    int l  = (idx / (DI / 4)) % LL;
    int b  = idx / ((DI / 4) * LL);

    float4 acc = *(const float4*)(cb + d4);
    // weights for the 4 channels: cw[(d)*KC + k]
    float4 w0 = *(const float4*)(cw + (d4 + 0) * KC);
    float4 w1 = *(const float4*)(cw + (d4 + 1) * KC);
    float4 w2 = *(const float4*)(cw + (d4 + 2) * KC);
    float4 w3 = *(const float4*)(cw + (d4 + 3) * KC);
    const float wk0[4] = {w0.x, w0.y, w0.z, w0.w};
    const float wk1[4] = {w1.x, w1.y, w1.z, w1.w};
    const float wk2[4] = {w2.x, w2.y, w2.z, w2.w};
    const float wk3[4] = {w3.x, w3.y, w3.z, w3.w};

#pragma unroll
    for (int k = 0; k < KC; k++) {
        int lp = rev ? (l + (KC - 1) - k) : (l - (KC - 1) + k);
        if (lp >= 0 && lp < LL) {
            float4 v = *(const float4*)(xz + ((size_t)(b * LL + lp)) * 2 * DI + d4);
            acc.x = fmaf(wk0[k], v.x, acc.x);
            acc.y = fmaf(wk1[k], v.y, acc.y);
            acc.z = fmaf(wk2[k], v.z, acc.z);
            acc.w = fmaf(wk3[k], v.w, acc.w);
        }
    }
    acc.x *= 1.f / (1.f + __expf(-acc.x));
    acc.y *= 1.f / (1.f + __expf(-acc.y));
    acc.z *= 1.f / (1.f + __expf(-acc.z));
    acc.w *= 1.f / (1.f + __expf(-acc.w));
    *(float4*)(xc + (size_t)idx * 4) = acc;
}

// ===========================================================================
// Fused selective scan + C-dot + D skip + SiLU(z) gating.
// Serial chain = one FFMA per step; per-step h*C products go to smem and are
// reduced over states in a separate parallel pass (no shfl in the chain).
// ===========================================================================
#define SCH 32
#define SCD 16

__global__ void __launch_bounds__(256) scan_kernel(
                            const float* __restrict__ dt,
                            const float* __restrict__ xc,
                            const float* __restrict__ xz,
                            const float* __restrict__ xdbl,
                            const float* __restrict__ Alog,
                            const float* __restrict__ Dp,
                            float* __restrict__ yg, int rev)
{
    __shared__ float2 s_dx[SCH][SCD];          // (dt, xc)
    __shared__ float  s_z [SCH][SCD];
    __shared__ float2 s_bc[SCH][SSN];          // (B, C)
    __shared__ float  s_c [SCH][SCD][SSN + 1]; // h*C products, padded stride 17
    __shared__ float  s_D [SCD];

    const int tid = threadIdx.x;
    const int cd = tid >> 4;      // chain within block: 0..15
    const int s  = tid & 15;      // state index
    const int d0 = blockIdx.x * SCD;
    const int b  = blockIdx.y;
    const int d  = d0 + cd;

    const float Aneg = -__expf(Alog[(size_t)d * SSN + s]);
    if (tid < SCD) s_D[tid] = Dp[d0 + tid];

    float h = 0.f;

    for (int t0 = 0; t0 < LL; t0 += SCH) {
        // Stage (dt,xc) + z tiles
#pragma unroll
        for (int it = 0; it < SCH * SCD / 256; it++) {
            int idx = tid + it * 256;
            int j = idx / SCD, dl = idx % SCD;
            int p = rev ? (LL - 1 - (t0 + j)) : (t0 + j);
            size_t row = (size_t)(b * LL + p);
            s_dx[j][dl] = make_float2(dt[row * DI + d0 + dl], xc[row * DI + d0 + dl]);
            s_z [j][dl] = xz[row * 2 * DI + DI + d0 + dl];
        }
        // Stage (B,C) tiles (cols 32..63 of x_dbl)
#pragma unroll
        for (int it = 0; it < SCH * SSN / 256; it++) {
            int idx = tid + it * 256;
            int j = idx / SSN, c = idx % SSN;
            int p = rev ? (LL - 1 - (t0 + j)) : (t0 + j);
            const float* base = xdbl + (size_t)(b * LL + p) * 64 + RR;
            s_bc[j][c] = make_float2(base[c], base[SSN + c]);
        }
        __syncthreads();

        // Sequential scan: only h-FFMA is serial; products parked in smem
#pragma unroll 8
        for (int j = 0; j < SCH; j++) {
            float2 dx = s_dx[j][cd];
            float2 bc = s_bc[j][s];
            float dA = __expf(dx.x * Aneg);
            h = fmaf(dA, h, dx.x * dx.y * bc.x);
            s_c[j][cd][s] = h * bc.y;
        }
        __syncthreads();

        // Parallel state-reduction + D skip + SiLU(z) gate + store
#pragma unroll
        for (int it = 0; it < SCH * SCD / 256; it++) {
            int idx = tid + it * 256;
            int j = idx / SCD, dl = idx % SCD;
            float sum = 0.f;
#pragma unroll
            for (int ss = 0; ss < SSN; ss++) sum += s_c[j][dl][ss];
            float y = fmaf(s_dx[j][dl].y, s_D[dl], sum);
            float zv = s_z[j][dl];
            y *= zv / (1.f + __expf(-zv));
            int p = rev ? (LL - 1 - (t0 + j)) : (t0 + j);
            yg[(size_t)(b * LL + p) * DI + d0 + dl] = y;
        }
        __syncthreads();
    }
}

// ===========================================================================
// LayerNorm, copy, zero
// ===========================================================================
__global__ void layernorm_kernel(const float* __restrict__ acc,
                                 const float* __restrict__ g,
                                 const float* __restrict__ bta,
                                 float* __restrict__ out)
{
    __shared__ float red[256];
    int row = blockIdx.x;
    int t = threadIdx.x;
    const float* rp = acc + (size_t)row * NN;

    float v0 = rp[t];
    float v1 = rp[t + 256];

    red[t] = v0 + v1;
    __syncthreads();
    for (int o = 128; o > 0; o >>= 1) {
        if (t < o) red[t] += red[t + o];
        __syncthreads();
    }
    float mu = red[0] * (1.f / NN);
    __syncthreads();

    float c0 = v0 - mu, c1 = v1 - mu;
    red[t] = c0 * c0 + c1 * c1;
    __syncthreads();
    for (int o = 128; o > 0; o >>= 1) {
        if (t < o) red[t] += red[t + o];
        __syncthreads();
    }
    float inv = rsqrtf(red[0] * (1.f / NN) + EPS);

    float* op = out + (size_t)row * NN;
    op[t]       = c0 * inv * g[t]       + bta[t];
    op[t + 256] = c1 * inv * g[t + 256] + bta[t + 256];
}

__global__ void copy_kernel(float* __restrict__ dst, const float* __restrict__ src, int n4)
{
    int i = blockIdx.x * blockDim.x + threadIdx.x;
    if (i < n4) ((float4*)dst)[i] = ((const float4*)src)[i];
}

__global__ void zero_kernel(float* __restrict__ dst, int n)
{
    int i = blockIdx.x * blockDim.x + threadIdx.x;
    if (i < n) dst[i] = 0.f;
}

// ===========================================================================
extern "C" void kernel_launch(void* const* d_in, const int* in_sizes, int n_in,
                              void* d_out, int out_size)
{
    const float* x    = (const float*)d_in[0];
    const float* inw  = (const float*)d_in[1];
    const float* cw   = (const float*)d_in[2];
    const float* cb   = (const float*)d_in[3];
    const float* xw   = (const float*)d_in[4];
    const float* dtw  = (const float*)d_in[5];
    const float* dtb  = (const float*)d_in[6];
    const float* Alog = (const float*)d_in[7];
    const float* Dp   = (const float*)d_in[8];
    const float* ow   = (const float*)d_in[9];
    const float* lng  = (const float*)d_in[10];
    const float* lnb  = (const float*)d_in[11];

    float *xz, *xc, *xdbl, *dt, *yg, *acc, *cur;
    cudaGetSymbolAddress((void**)&xz,   g_xz);
    cudaGetSymbolAddress((void**)&xc,   g_xc);
    cudaGetSymbolAddress((void**)&xdbl, g_xdbl);
    cudaGetSymbolAddress((void**)&dt,   g_dt);
    cudaGetSymbolAddress((void**)&yg,   g_yg);
    cudaGetSymbolAddress((void**)&acc,  g_acc);
    cudaGetSymbolAddress((void**)&cur,  g_cur);

    const float* layer_in = x;

    for (int l = 0; l < NLAYER; l++) {
        copy_kernel<<<(MROWS * NN / 4 + 255) / 256, 256>>>(acc, layer_in, MROWS * NN / 4);

        for (int dir = 0; dir < 2; dir++) {
            int i = 2 * l + dir;

            // in_proj: xz[2048,2048] = layer_in[2048,512] @ W[2048,512]^T (fp16x2 HMMA)
            hgemm_nt<<<dim3(2 * DI / 128, MROWS / 128, 1), 256>>>(
                layer_in, inw + (size_t)i * 2 * DI * NN, xz,
                NN, NN, NN, 2 * DI, 0);

            // depthwise causal conv + SiLU (float4 over d)
            conv_silu_kernel<<<(BB * LL * DI / 4 + 255) / 256, 256>>>(
                xz, cw + (size_t)i * DI * KC, cb + (size_t)i * DI, xc, dir);

            // xproj (split-K=8, atomic accumulate): x_dbl[2048,64]
            zero_kernel<<<(MROWS * 64 + 255) / 256, 256>>>(xdbl, MROWS * 64);
            sgemm_nt<64, 64, 16, 4, 4, 2><<<dim3(1, MROWS / 64, 8), 256>>>(
                xc, xw + (size_t)i * 64 * DI, xdbl,
                MROWS, 64, DI, DI, DI, 64, nullptr);

            // dtproj + bias + softplus: dt[2048,1024]
            sgemm_nt<128, 64, 16, 8, 4, 3><<<dim3(DI / 64, MROWS / 128, 1), 256>>>(
                xdbl, dtw + (size_t)i * DI * RR, dt,
                MROWS, DI, RR, 64, RR, DI, dtb + (size_t)i * DI);

            // fused selective scan + gate (serial chain = 1 FFMA/step)
            scan_kernel<<<dim3(DI / SCD, BB), 256>>>(
                dt, xc, xz, xdbl, Alog + (size_t)i * DI * SSN, Dp + (size_t)i * DI, yg, dir);

            // out_proj, split-K=2 atomic accumulate into residual (fp16x2 HMMA)
            hgemm_nt<<<dim3(NN / 128, MROWS / 128, 2), 256>>>(
                yg, ow + (size_t)i * NN * DI, acc,
                DI, DI, DI, NN, 2);
        }

        float* lnout = (l == NLAYER - 1) ? (float*)d_out : cur;
        layernorm_kernel<<<MROWS, 256>>>(acc, lng + (size_t)l * NN, lnb + (size_t)l * NN, lnout);
        layer_in = cur;
    }
}

// round 7
// speedup vs baseline: 2.2539x; 1.0170x over previous
#include <cuda_runtime.h>
#include <cuda_fp16.h>
#include <math.h>
#include <stdint.h>

// Problem constants
#define BB 2
#define LL 1024
#define NN 512
#define NLAYER 2
#define DI 1024
#define SSN 16
#define KC 4
#define RR 32
#define EPS 1e-5f
#define MROWS (BB*LL)   // 2048

// Per-direction buffer sizes (elements)
#define XZ_SZ ((size_t)MROWS * 2 * DI)
#define XC_SZ ((size_t)MROWS * DI)
#define XD_SZ ((size_t)MROWS * 64)
#define YG_SZ ((size_t)MROWS * DI)

// Scratch buffers (static device globals; no runtime allocation)
__device__ __align__(256) float g_xz  [2 * XZ_SZ];
__device__ __align__(256) float g_xc  [2 * XC_SZ];
__device__ __align__(256) float g_xdbl[2 * XD_SZ];
__device__ __align__(256) float g_yg  [2 * YG_SZ];
__device__ __align__(256) float g_acc [(size_t)MROWS * NN];
__device__ __align__(256) float g_cur [(size_t)MROWS * NN];

// ===========================================================================
// Helpers
// ===========================================================================
static __device__ __forceinline__ uint32_t smem_u32(const void* p) {
    uint32_t a;
    asm("{ .reg .u64 t; cvta.to.shared.u64 t, %1; cvt.u32.u64 %0, t; }" : "=r"(a) : "l"(p));
    return a;
}

static __device__ __forceinline__ void ldsm4(uint32_t* r, uint32_t addr) {
    asm volatile("ldmatrix.sync.aligned.m8n8.x4.shared.b16 {%0,%1,%2,%3}, [%4];"
        : "=r"(r[0]), "=r"(r[1]), "=r"(r[2]), "=r"(r[3]) : "r"(addr));
}

static __device__ __forceinline__ void mma_f16(float* c, const uint32_t* a,
                                               uint32_t b0, uint32_t b1) {
    asm volatile(
        "mma.sync.aligned.m16n8k16.row.col.f32.f16.f16.f32 "
        "{%0,%1,%2,%3}, {%4,%5,%6,%7}, {%8,%9}, {%0,%1,%2,%3};"
        : "+f"(c[0]), "+f"(c[1]), "+f"(c[2]), "+f"(c[3])
        : "r"(a[0]), "r"(a[1]), "r"(a[2]), "r"(a[3]), "r"(b0), "r"(b1));
}

#define CP_ASYNC16(smem, gptr) \
    asm volatile("cp.async.cg.shared.global [%0], [%1], 16;" :: "r"(smem), "l"(gptr) : "memory")
#define CP_COMMIT() asm volatile("cp.async.commit_group;" ::: "memory")

// ===========================================================================
// fp16x2 NT GEMM, cp.async double-buffered: C (+)= A @ B^T, fp32 I/O.
// A -> (hi,lo) fp16 split; B -> fp16. 2 MMAs/k-step. Block 128x128, 8 warps.
// blockIdx.z = dir*nsplit + kslice; per-dir pointer strides aZ/bZ/cZ.
// epi: 0 = store, 1 = add, 2 = atomicAdd
// ===========================================================================
#define PAD 40
#define HG_STAGE 16384                       // 128*32*4 bytes per fp32 tile
#define HG_TILE  (128*PAD)                   // fp16 elems per tile
#define HG_SMEM  (4*HG_STAGE + 3*HG_TILE*2)  // 65536 + 30720 = 96256 bytes

__global__ void __launch_bounds__(256, 2) hgemm_nt(
    const float* __restrict__ A, const float* __restrict__ Bw, float* __restrict__ C,
    int K, int lda, int ldb, int ldc, int epi, int nsplit,
    size_t aZ, size_t bZ, size_t cZ)
{
    extern __shared__ char dsm[];
    float* stA[2] = {(float*)dsm,                  (float*)(dsm + 2*HG_STAGE)};
    float* stB[2] = {(float*)(dsm + HG_STAGE),     (float*)(dsm + 3*HG_STAGE)};
    __half* sAhi = (__half*)(dsm + 4*HG_STAGE);
    __half* sAlo = sAhi + HG_TILE;
    __half* sBhi = sAlo + HG_TILE;

    const int tid = threadIdx.x;
    const int wid = tid >> 5, lane = tid & 31;
    const int wm = wid >> 2, wn = wid & 3;
    const int bm = blockIdx.y * 128, bn = blockIdx.x * 128;
    const int dir = blockIdx.z / nsplit;
    const int ksl = blockIdx.z % nsplit;
    A  += (size_t)dir * aZ;
    Bw += (size_t)dir * bZ;
    C  += (size_t)dir * cZ;
    const int kslice = K / nsplit;
    const int kbeg = ksl * kslice;
    const int nch = kslice / 32;

    const uint32_t uA[2] = {smem_u32(stA[0]), smem_u32(stA[1])};
    const uint32_t uB[2] = {smem_u32(stB[0]), smem_u32(stB[1])};
    const uint32_t aAhi = smem_u32(sAhi);
    const uint32_t aAlo = smem_u32(sAlo);
    const uint32_t aBhi = smem_u32(sBhi);

    const int lrow = lane & 15;
    const int lchunk = lane >> 4;

    float acc[4][4][4];
#pragma unroll
    for (int i = 0; i < 4; i++)
#pragma unroll
        for (int j = 0; j < 4; j++)
#pragma unroll
            for (int q = 0; q < 4; q++) acc[i][j][q] = 0.f;

    auto issue_chunk = [&](int kc, int buf) {
        const float* Ab = A + (size_t)bm * lda + kbeg + kc * 32;
        const float* Bb = Bw + (size_t)bn * ldb + kbeg + kc * 32;
#pragma unroll
        for (int i = 0; i < 4; i++) {
            int idx = tid + i * 256;
            int r = idx >> 3, c = (idx & 7) * 4;
            uint32_t off = (uint32_t)(r * 32 + c) * 4;
            CP_ASYNC16(uA[buf] + off, Ab + (size_t)r * lda + c);
            CP_ASYNC16(uB[buf] + off, Bb + (size_t)r * ldb + c);
        }
        CP_COMMIT();
    };

    issue_chunk(0, 0);

    for (int kc = 0; kc < nch; kc++) {
        if (kc + 1 < nch) {
            issue_chunk(kc + 1, (kc + 1) & 1);
            asm volatile("cp.async.wait_group 1;" ::: "memory");
        } else {
            asm volatile("cp.async.wait_group 0;" ::: "memory");
        }
        __syncthreads();   // stage[kc&1] visible; prev MMA done (tiles reusable)

        // Convert fp32 stage -> fp16 tiles
        const float* sA = stA[kc & 1];
        const float* sB = stB[kc & 1];
#pragma unroll
        for (int i = 0; i < 4; i++) {
            int idx = tid + i * 256;
            int r = idx >> 3, c = (idx & 7) * 4;
            int soff = r * 32 + c;
            int toff = r * PAD + c;
            float4 va = *(const float4*)(sA + soff);
            __half2 h01 = __floats2half2_rn(va.x, va.y);
            __half2 h23 = __floats2half2_rn(va.z, va.w);
            float2 f01 = __half22float2(h01);
            float2 f23 = __half22float2(h23);
            *(__half2*)(sAhi + toff)     = h01;
            *(__half2*)(sAhi + toff + 2) = h23;
            *(__half2*)(sAlo + toff)     = __floats2half2_rn(va.x - f01.x, va.y - f01.y);
            *(__half2*)(sAlo + toff + 2) = __floats2half2_rn(va.z - f23.x, va.w - f23.y);
            float4 vb = *(const float4*)(sB + soff);
            *(__half2*)(sBhi + toff)     = __floats2half2_rn(vb.x, vb.y);
            *(__half2*)(sBhi + toff + 2) = __floats2half2_rn(vb.z, vb.w);
        }
        __syncthreads();

#pragma unroll
        for (int ks = 0; ks < 2; ks++) {
            uint32_t ahi[4][4], alo[4][4];
#pragma unroll
            for (int mt = 0; mt < 4; mt++) {
                uint32_t off = (uint32_t)((wm * 64 + mt * 16 + lrow) * PAD
                                          + ks * 16 + lchunk * 8) * 2;
                ldsm4(ahi[mt], aAhi + off);
                ldsm4(alo[mt], aAlo + off);
            }
            uint32_t bh[2][4];
#pragma unroll
            for (int np = 0; np < 2; np++) {
                uint32_t off = (uint32_t)((wn * 32 + np * 16 + lrow) * PAD
                                          + ks * 16 + lchunk * 8) * 2;
                ldsm4(bh[np], aBhi + off);
            }
#pragma unroll
            for (int mt = 0; mt < 4; mt++)
#pragma unroll
                for (int np = 0; np < 2; np++)
#pragma unroll
                    for (int sub = 0; sub < 2; sub++) {
                        int nt = np * 2 + sub;
                        mma_f16(acc[mt][nt], ahi[mt], bh[np][sub], bh[np][sub + 2]);
                        mma_f16(acc[mt][nt], alo[mt], bh[np][sub], bh[np][sub + 2]);
                    }
        }
    }

    // Epilogue
    const int r0 = lane >> 2;
    const int c0 = (lane & 3) * 2;
#pragma unroll
    for (int mt = 0; mt < 4; mt++) {
#pragma unroll
        for (int nt = 0; nt < 4; nt++) {
            int m = bm + wm * 64 + mt * 16 + r0;
            int n = bn + wn * 32 + nt * 8 + c0;
            float* p0 = &C[(size_t)m * ldc + n];
            float* p1 = &C[(size_t)(m + 8) * ldc + n];
            float* a = acc[mt][nt];
            if (epi == 0) {
                *(float2*)p0 = make_float2(a[0], a[1]);
                *(float2*)p1 = make_float2(a[2], a[3]);
            } else if (epi == 1) {
                float2 o0 = *(float2*)p0, o1 = *(float2*)p1;
                o0.x += a[0]; o0.y += a[1];
                o1.x += a[2]; o1.y += a[3];
                *(float2*)p0 = o0; *(float2*)p1 = o1;
            } else {
                atomicAdd(p0, a[0]); atomicAdd(p0 + 1, a[1]);
                atomicAdd(p1, a[2]); atomicAdd(p1 + 1, a[3]);
            }
        }
    }
}

// ===========================================================================
// CUDA-core SGEMM (xproj only now): C = A @ B^T, z = dir (aZ/bZ/cZ strides)
// ===========================================================================
template<int BM, int BN, int BK, int TM, int TN>
__global__ void sgemm_nt(const float* __restrict__ A, const float* __restrict__ Bm,
                         float* __restrict__ C, int M, int N, int Kt,
                         int lda, int ldb, int ldc,
                         size_t aZ, size_t bZ, size_t cZ)
{
    constexpr int TX = BN / TN;
    constexpr int TY = BM / TM;
    constexpr int THREADS = TX * TY;
    __shared__ float As[BK][BM + 4];
    __shared__ float Bs[BK][BN + 4];

    const int tid = threadIdx.x;
    const int tx = tid % TX;
    const int ty = tid / TX;
    const int bm = blockIdx.y * BM;
    const int bn = blockIdx.x * BN;
    const int dir = blockIdx.z;
    A += (size_t)dir * aZ;
    Bm += (size_t)dir * bZ;
    C += (size_t)dir * cZ;

    float acc[TM][TN];
#pragma unroll
    for (int m = 0; m < TM; m++)
#pragma unroll
        for (int n = 0; n < TN; n++) acc[m][n] = 0.f;

    for (int k0 = 0; k0 < Kt; k0 += BK) {
#pragma unroll
        for (int i = 0; i < BM * BK / 4 / THREADS; i++) {
            int idx = tid + i * THREADS;
            int r = idx / (BK / 4);
            int c4 = idx % (BK / 4);
            float4 v = *(const float4*)&A[(size_t)(bm + r) * lda + k0 + c4 * 4];
            As[c4 * 4 + 0][r] = v.x;
            As[c4 * 4 + 1][r] = v.y;
            As[c4 * 4 + 2][r] = v.z;
            As[c4 * 4 + 3][r] = v.w;
        }
#pragma unroll
        for (int i = 0; i < BN * BK / 4 / THREADS; i++) {
            int idx = tid + i * THREADS;
            int r = idx / (BK / 4);
            int c4 = idx % (BK / 4);
            float4 v = *(const float4*)&Bm[(size_t)(bn + r) * ldb + k0 + c4 * 4];
            Bs[c4 * 4 + 0][r] = v.x;
            Bs[c4 * 4 + 1][r] = v.y;
            Bs[c4 * 4 + 2][r] = v.z;
            Bs[c4 * 4 + 3][r] = v.w;
        }
        __syncthreads();

#pragma unroll
        for (int k = 0; k < BK; k++) {
            float ra[TM], rb[TN];
#pragma unroll
            for (int m = 0; m < TM; m++) ra[m] = As[k][ty * TM + m];
#pragma unroll
            for (int n = 0; n < TN; n++) rb[n] = Bs[k][tx * TN + n];
#pragma unroll
            for (int m = 0; m < TM; m++)
#pragma unroll
                for (int n = 0; n < TN; n++)
                    acc[m][n] = fmaf(ra[m], rb[n], acc[m][n]);
        }
        __syncthreads();
    }

#pragma unroll
    for (int m = 0; m < TM; m++) {
        int r = bm + ty * TM + m;
#pragma unroll
        for (int n = 0; n < TN; n++) {
            int c = bn + tx * TN + n;
            C[(size_t)r * ldc + c] = acc[m][n];
        }
    }
}

// ===========================================================================
// Causal depthwise conv (K=4) + SiLU, float4 over d. blockIdx.y = dir.
// ===========================================================================
__global__ void conv_silu_kernel(const float* __restrict__ xz,
                                 const float* __restrict__ cw,
                                 const float* __restrict__ cb,
                                 float* __restrict__ xc)
{
    const int dir = blockIdx.y;
    xz += (size_t)dir * XZ_SZ;
    cw += (size_t)dir * DI * KC;
    cb += (size_t)dir * DI;
    xc += (size_t)dir * XC_SZ;
    const int rev = dir;

    int idx = blockIdx.x * blockDim.x + threadIdx.x;   // over B*L*DI/4
    if (idx >= BB * LL * DI / 4) return;
    int d4 = (idx % (DI / 4)) * 4;
    int l  = (idx / (DI / 4)) % LL;
    int b  = idx / ((DI / 4) * LL);

    float4 acc = *(const float4*)(cb + d4);
    float4 w0 = *(const float4*)(cw + (d4 + 0) * KC);
    float4 w1 = *(const float4*)(cw + (d4 + 1) * KC);
    float4 w2 = *(const float4*)(cw + (d4 + 2) * KC);
    float4 w3 = *(const float4*)(cw + (d4 + 3) * KC);
    const float wk0[4] = {w0.x, w0.y, w0.z, w0.w};
    const float wk1[4] = {w1.x, w1.y, w1.z, w1.w};
    const float wk2[4] = {w2.x, w2.y, w2.z, w2.w};
    const float wk3[4] = {w3.x, w3.y, w3.z, w3.w};

#pragma unroll
    for (int k = 0; k < KC; k++) {
        int lp = rev ? (l + (KC - 1) - k) : (l - (KC - 1) + k);
        if (lp >= 0 && lp < LL) {
            float4 v = *(const float4*)(xz + ((size_t)(b * LL + lp)) * 2 * DI + d4);
            acc.x = fmaf(wk0[k], v.x, acc.x);
            acc.y = fmaf(wk1[k], v.y, acc.y);
            acc.z = fmaf(wk2[k], v.z, acc.z);
            acc.w = fmaf(wk3[k], v.w, acc.w);
        }
    }
    acc.x *= 1.f / (1.f + __expf(-acc.x));
    acc.y *= 1.f / (1.f + __expf(-acc.y));
    acc.z *= 1.f / (1.f + __expf(-acc.z));
    acc.w *= 1.f / (1.f + __expf(-acc.w));
    *(float4*)(xc + (size_t)idx * 4) = acc;
}

// ===========================================================================
// Fused dtproj + softplus + selective scan + C-dot + D skip + SiLU(z) gate.
// blockIdx.z = dir. dtw row for each thread's channel preloaded to registers.
// s_raw (dt-proj inputs) overlays the s_c region: temporally disjoint phases.
// ===========================================================================
#define SCH 32
#define SCD 16

__global__ void __launch_bounds__(256) scan_kernel(
                            const float* __restrict__ xc,
                            const float* __restrict__ xz,
                            const float* __restrict__ xdbl,
                            const float* __restrict__ Alog,
                            const float* __restrict__ Dp,
                            const float* __restrict__ dtw,
                            const float* __restrict__ dtb,
                            float* __restrict__ yg)
{
    __shared__ float2 s_dx[SCH][SCD];          // (.x = dt, .y = xc)   4096 B
    __shared__ float  s_z [SCH][SCD];          //                      2048 B
    __shared__ float2 s_bc[SCH][SSN];          // (B, C)               4096 B
    __shared__ float  s_c [SCH][SCD][SSN + 1]; // h*C products        34816 B
    // s_raw overlays s_c (disjoint phases): xdbl[:, 0:32] staging
    float (*s_raw)[RR] = (float (*)[RR])(&s_c[0][0][0]);

    const int tid = threadIdx.x;
    const int cd = tid >> 4;      // chain within block
    const int s  = tid & 15;      // state index
    const int d0 = blockIdx.x * SCD;
    const int b  = blockIdx.y;
    const int dir = blockIdx.z;
    const int rev = dir;
    const int d  = d0 + cd;

    xc   += (size_t)dir * XC_SZ;
    xz   += (size_t)dir * XZ_SZ;
    xdbl += (size_t)dir * XD_SZ;
    yg   += (size_t)dir * YG_SZ;
    Alog += (size_t)dir * DI * SSN;
    Dp   += (size_t)dir * DI;
    dtw  += (size_t)dir * DI * RR;
    dtb  += (size_t)dir * DI;

    const float Aneg = -__expf(Alog[(size_t)d * SSN + s]);

    // Per-thread channel for dt-dot and reduction: dl == tid & 15 everywhere
    const int mydl = tid & 15;
    const float myD = Dp[d0 + mydl];
    float wdt[RR];
#pragma unroll
    for (int k = 0; k < RR; k++) wdt[k] = dtw[(size_t)(d0 + mydl) * RR + k];
    const float mydtb = dtb[d0 + mydl];

    float h = 0.f;

    for (int t0 = 0; t0 < LL; t0 += SCH) {
        // Stage xc / z
#pragma unroll
        for (int it = 0; it < SCH * SCD / 256; it++) {
            int idx = tid + it * 256;
            int j = idx / SCD, dl = idx % SCD;
            int p = rev ? (LL - 1 - (t0 + j)) : (t0 + j);
            size_t row = (size_t)(b * LL + p);
            s_dx[j][dl].y = xc[row * DI + d0 + dl];
            s_z [j][dl]   = xz[row * 2 * DI + DI + d0 + dl];
        }
        // Stage xdbl full 64 cols: 0..31 -> s_raw (overlay), 32..47 -> B, 48..63 -> C
#pragma unroll
        for (int it = 0; it < SCH * 64 / 256; it++) {
            int idx = tid + it * 256;
            int j = idx / 64, c = idx % 64;
            int p = rev ? (LL - 1 - (t0 + j)) : (t0 + j);
            float v = xdbl[(size_t)(b * LL + p) * 64 + c];
            if (c < RR)            s_raw[j][c] = v;
            else if (c < RR + SSN) s_bc[j][c - RR].x = v;
            else                   s_bc[j][c - RR - SSN].y = v;
        }
        __syncthreads();

        // dt = softplus(xdbl[:, :32] @ dtw[d] + dtb[d]) — 2 (j, dl) pairs/thread
#pragma unroll
        for (int it = 0; it < SCH * SCD / 256; it++) {
            int idx = tid + it * 256;
            int j = idx / SCD;                 // dl == mydl by construction
            float u = mydtb;
#pragma unroll
            for (int k = 0; k < RR; k++) u = fmaf(s_raw[j][k], wdt[k], u);
            float sp = (u > 0.f) ? (u + log1pf(__expf(-u))) : log1pf(__expf(u));
            s_dx[j][mydl].x = sp;
        }
        __syncthreads();   // s_raw fully consumed; s_c region may now be written

        // Serial scan: only the h-FFMA is serial
#pragma unroll 8
        for (int j = 0; j < SCH; j++) {
            float2 dx = s_dx[j][cd];
            float2 bc = s_bc[j][s];
            float dA = __expf(dx.x * Aneg);
            h = fmaf(dA, h, dx.x * dx.y * bc.x);
            s_c[j][cd][s] = h * bc.y;
        }
        __syncthreads();

        // Parallel state-reduction + D skip + SiLU(z) gate + store (dl == mydl)
#pragma unroll
        for (int it = 0; it < SCH * SCD / 256; it++) {
            int idx = tid + it * 256;
            int j = idx / SCD, dl = idx % SCD;
            float sum = 0.f;
#pragma unroll
            for (int ss = 0; ss < SSN; ss++) sum += s_c[j][dl][ss];
            float y = fmaf(s_dx[j][dl].y, myD, sum);
            float zv = s_z[j][dl];
            y *= zv / (1.f + __expf(-zv));
            int p = rev ? (LL - 1 - (t0 + j)) : (t0 + j);
            yg[(size_t)(b * LL + p) * DI + d0 + dl] = y;
        }
        __syncthreads();
    }
}

// ===========================================================================
// LayerNorm + copy
// ===========================================================================
__global__ void layernorm_kernel(const float* __restrict__ acc,
                                 const float* __restrict__ g,
                                 const float* __restrict__ bta,
                                 float* __restrict__ out)
{
    __shared__ float red[256];
    int row = blockIdx.x;
    int t = threadIdx.x;
    const float* rp = acc + (size_t)row * NN;

    float v0 = rp[t];
    float v1 = rp[t + 256];

    red[t] = v0 + v1;
    __syncthreads();
    for (int o = 128; o > 0; o >>= 1) {
        if (t < o) red[t] += red[t + o];
        __syncthreads();
    }
    float mu = red[0] * (1.f / NN);
    __syncthreads();

    float c0 = v0 - mu, c1 = v1 - mu;
    red[t] = c0 * c0 + c1 * c1;
    __syncthreads();
    for (int o = 128; o > 0; o >>= 1) {
        if (t < o) red[t] += red[t + o];
        __syncthreads();
    }
    float inv = rsqrtf(red[0] * (1.f / NN) + EPS);

    float* op = out + (size_t)row * NN;
    op[t]       = c0 * inv * g[t]       + bta[t];
    op[t + 256] = c1 * inv * g[t + 256] + bta[t + 256];
}

__global__ void copy_kernel(float* __restrict__ dst, const float* __restrict__ src, int n4)
{
    int i = blockIdx.x * blockDim.x + threadIdx.x;
    if (i < n4) ((float4*)dst)[i] = ((const float4*)src)[i];
}

// ===========================================================================
extern "C" void kernel_launch(void* const* d_in, const int* in_sizes, int n_in,
                              void* d_out, int out_size)
{
    const float* x    = (const float*)d_in[0];
    const float* inw  = (const float*)d_in[1];
    const float* cw   = (const float*)d_in[2];
    const float* cb   = (const float*)d_in[3];
    const float* xw   = (const float*)d_in[4];
    const float* dtw  = (const float*)d_in[5];
    const float* dtb  = (const float*)d_in[6];
    const float* Alog = (const float*)d_in[7];
    const float* Dp   = (const float*)d_in[8];
    const float* ow   = (const float*)d_in[9];
    const float* lng  = (const float*)d_in[10];
    const float* lnb  = (const float*)d_in[11];

    float *xz, *xc, *xdbl, *yg, *acc, *cur;
    cudaGetSymbolAddress((void**)&xz,   g_xz);
    cudaGetSymbolAddress((void**)&xc,   g_xc);
    cudaGetSymbolAddress((void**)&xdbl, g_xdbl);
    cudaGetSymbolAddress((void**)&yg,   g_yg);
    cudaGetSymbolAddress((void**)&acc,  g_acc);
    cudaGetSymbolAddress((void**)&cur,  g_cur);

    static int smem_set = 0;
    if (!smem_set) {
        cudaFuncSetAttribute(hgemm_nt, cudaFuncAttributeMaxDynamicSharedMemorySize, HG_SMEM);
        smem_set = 1;
    }

    const float* layer_in = x;

    for (int l = 0; l < NLAYER; l++) {
        const size_t i0 = 2 * l;  // weight index of fwd direction

        // acc = residual
        copy_kernel<<<(MROWS * NN / 4 + 255) / 256, 256>>>(acc, layer_in, MROWS * NN / 4);

        // in_proj, both dirs: xz[dir] = layer_in @ inw[i0+dir]^T
        hgemm_nt<<<dim3(2 * DI / 128, MROWS / 128, 2), 256, HG_SMEM>>>(
            layer_in, inw + i0 * 2 * DI * NN, xz,
            NN, NN, NN, 2 * DI, /*epi*/0, /*nsplit*/1,
            0, (size_t)2 * DI * NN, XZ_SZ);

        // conv + SiLU, both dirs
        conv_silu_kernel<<<dim3((BB * LL * DI / 4 + 255) / 256, 2), 256>>>(
            xz, cw + i0 * DI * KC, cb + i0 * DI, xc);

        // xproj, both dirs: xdbl[dir] = xc[dir] @ xw[i0+dir]^T
        sgemm_nt<64, 64, 16, 4, 4><<<dim3(1, MROWS / 64, 2), 256>>>(
            xc, xw + i0 * 64 * DI, xdbl,
            MROWS, 64, DI, DI, DI, 64,
            XC_SZ, (size_t)64 * DI, XD_SZ);

        // fused dtproj + scan + gate, both dirs
        scan_kernel<<<dim3(DI / SCD, BB, 2), 256>>>(
            xc, xz, xdbl,
            Alog + i0 * DI * SSN, Dp + i0 * DI,
            dtw + i0 * DI * RR, dtb + i0 * DI, yg);

        // out_proj, both dirs x split-K=2, atomic into residual
        hgemm_nt<<<dim3(NN / 128, MROWS / 128, 4), 256, HG_SMEM>>>(
            yg, ow + i0 * NN * DI, acc,
            DI, DI, DI, NN, /*epi*/2, /*nsplit*/2,
            YG_SZ, (size_t)NN * DI, 0);

        float* lnout = (l == NLAYER - 1) ? (float*)d_out : cur;
        layernorm_kernel<<<MROWS, 256>>>(acc, lng + (size_t)l * NN, lnb + (size_t)l * NN, lnout);
        layer_in = cur;
    }
}

// round 10
// speedup vs baseline: 2.4902x; 1.1048x over previous
#include <cuda_runtime.h>
#include <cuda_fp16.h>
#include <math.h>
#include <stdint.h>

// Problem constants
#define BB 2
#define LL 1024
#define NN 512
#define NLAYER 2
#define DI 1024
#define SSN 16
#define KC 4
#define RR 32
#define EPS 1e-5f
#define MROWS (BB*LL)   // 2048

// Per-direction buffer sizes (elements)
#define XZ_SZ ((size_t)MROWS * 2 * DI)
#define XC_SZ ((size_t)MROWS * DI)
#define XD_SZ ((size_t)MROWS * 64)
#define YG_SZ ((size_t)MROWS * DI)

// Scratch buffers (static device globals; no runtime allocation)
__device__ __align__(256) float g_xz  [2 * XZ_SZ];
__device__ __align__(256) float g_xc  [2 * XC_SZ];
__device__ __align__(256) float g_xdbl[2 * XD_SZ];
__device__ __align__(256) float g_yg  [2 * YG_SZ];
__device__ __align__(256) float g_acc [(size_t)MROWS * NN];
__device__ __align__(256) float g_cur [(size_t)MROWS * NN];

// ===========================================================================
// Helpers
// ===========================================================================
static __device__ __forceinline__ uint32_t smem_u32(const void* p) {
    uint32_t a;
    asm("{ .reg .u64 t; cvta.to.shared.u64 t, %1; cvt.u32.u64 %0, t; }" : "=r"(a) : "l"(p));
    return a;
}

static __device__ __forceinline__ void ldsm4(uint32_t* r, uint32_t addr) {
    asm volatile("ldmatrix.sync.aligned.m8n8.x4.shared.b16 {%0,%1,%2,%3}, [%4];"
        : "=r"(r[0]), "=r"(r[1]), "=r"(r[2]), "=r"(r[3]) : "r"(addr));
}

static __device__ __forceinline__ void mma_f16(float* c, const uint32_t* a,
                                               uint32_t b0, uint32_t b1) {
    asm volatile(
        "mma.sync.aligned.m16n8k16.row.col.f32.f16.f16.f32 "
        "{%0,%1,%2,%3}, {%4,%5,%6,%7}, {%8,%9}, {%0,%1,%2,%3};"
        : "+f"(c[0]), "+f"(c[1]), "+f"(c[2]), "+f"(c[3])
        : "r"(a[0]), "r"(a[1]), "r"(a[2]), "r"(a[3]), "r"(b0), "r"(b1));
}

#define CP_ASYNC16(smem, gptr) \
    asm volatile("cp.async.cg.shared.global [%0], [%1], 16;" :: "r"(smem), "l"(gptr) : "memory")
#define CP_COMMIT() asm volatile("cp.async.commit_group;" ::: "memory")

// ===========================================================================
// fp16x2 NT GEMM, cp.async double-buffered: C (+)= A @ B^T, fp32 I/O.
// A -> (hi,lo) fp16 split; B -> fp16. 2 MMAs/k-step. Block 128x128, 8 warps.
// blockIdx.z = dir*nsplit + kslice; per-dir pointer strides aZ/bZ/cZ.
// epi: 0 = store, 1 = add, 2 = atomicAdd
// ===========================================================================
#define PAD 40
#define HG_STAGE 16384                       // 128*32*4 bytes per fp32 tile
#define HG_TILE  (128*PAD)                   // fp16 elems per tile
#define HG_SMEM  (4*HG_STAGE + 3*HG_TILE*2)  // 65536 + 30720 = 96256 bytes

__global__ void __launch_bounds__(256, 2) hgemm_nt(
    const float* __restrict__ A, const float* __restrict__ Bw, float* __restrict__ C,
    int K, int lda, int ldb, int ldc, int epi, int nsplit,
    size_t aZ, size_t bZ, size_t cZ)
{
    extern __shared__ char dsm[];
    float* stA[2] = {(float*)dsm,                  (float*)(dsm + 2*HG_STAGE)};
    float* stB[2] = {(float*)(dsm + HG_STAGE),     (float*)(dsm + 3*HG_STAGE)};
    __half* sAhi = (__half*)(dsm + 4*HG_STAGE);
    __half* sAlo = sAhi + HG_TILE;
    __half* sBhi = sAlo + HG_TILE;

    const int tid = threadIdx.x;
    const int wid = tid >> 5, lane = tid & 31;
    const int wm = wid >> 2, wn = wid & 3;
    const int bm = blockIdx.y * 128, bn = blockIdx.x * 128;
    const int dir = blockIdx.z / nsplit;
    const int ksl = blockIdx.z % nsplit;
    A  += (size_t)dir * aZ;
    Bw += (size_t)dir * bZ;
    C  += (size_t)dir * cZ;
    const int kslice = K / nsplit;
    const int kbeg = ksl * kslice;
    const int nch = kslice / 32;

    const uint32_t uA[2] = {smem_u32(stA[0]), smem_u32(stA[1])};
    const uint32_t uB[2] = {smem_u32(stB[0]), smem_u32(stB[1])};
    const uint32_t aAhi = smem_u32(sAhi);
    const uint32_t aAlo = smem_u32(sAlo);
    const uint32_t aBhi = smem_u32(sBhi);

    const int lrow = lane & 15;
    const int lchunk = lane >> 4;

    float acc[4][4][4];
#pragma unroll
    for (int i = 0; i < 4; i++)
#pragma unroll
        for (int j = 0; j < 4; j++)
#pragma unroll
            for (int q = 0; q < 4; q++) acc[i][j][q] = 0.f;

    auto issue_chunk = [&](int kc, int buf) {
        const float* Ab = A + (size_t)bm * lda + kbeg + kc * 32;
        const float* Bb = Bw + (size_t)bn * ldb + kbeg + kc * 32;
#pragma unroll
        for (int i = 0; i < 4; i++) {
            int idx = tid + i * 256;
            int r = idx >> 3, c = (idx & 7) * 4;
            uint32_t off = (uint32_t)(r * 32 + c) * 4;
            CP_ASYNC16(uA[buf] + off, Ab + (size_t)r * lda + c);
            CP_ASYNC16(uB[buf] + off, Bb + (size_t)r * ldb + c);
        }
        CP_COMMIT();
    };

    issue_chunk(0, 0);

    for (int kc = 0; kc < nch; kc++) {
        if (kc + 1 < nch) {
            issue_chunk(kc + 1, (kc + 1) & 1);
            asm volatile("cp.async.wait_group 1;" ::: "memory");
        } else {
            asm volatile("cp.async.wait_group 0;" ::: "memory");
        }
        __syncthreads();   // stage[kc&1] visible; prev MMA done (tiles reusable)

        // Convert fp32 stage -> fp16 tiles
        const float* sA = stA[kc & 1];
        const float* sB = stB[kc & 1];
#pragma unroll
        for (int i = 0; i < 4; i++) {
            int idx = tid + i * 256;
            int r = idx >> 3, c = (idx & 7) * 4;
            int soff = r * 32 + c;
            int toff = r * PAD + c;
            float4 va = *(const float4*)(sA + soff);
            __half2 h01 = __floats2half2_rn(va.x, va.y);
            __half2 h23 = __floats2half2_rn(va.z, va.w);
            float2 f01 = __half22float2(h01);
            float2 f23 = __half22float2(h23);
            *(__half2*)(sAhi + toff)     = h01;
            *(__half2*)(sAhi + toff + 2) = h23;
            *(__half2*)(sAlo + toff)     = __floats2half2_rn(va.x - f01.x, va.y - f01.y);
            *(__half2*)(sAlo + toff + 2) = __floats2half2_rn(va.z - f23.x, va.w - f23.y);
            float4 vb = *(const float4*)(sB + soff);
            *(__half2*)(sBhi + toff)     = __floats2half2_rn(vb.x, vb.y);
            *(__half2*)(sBhi + toff + 2) = __floats2half2_rn(vb.z, vb.w);
        }
        __syncthreads();

#pragma unroll
        for (int ks = 0; ks < 2; ks++) {
            uint32_t ahi[4][4], alo[4][4];
#pragma unroll
            for (int mt = 0; mt < 4; mt++) {
                uint32_t off = (uint32_t)((wm * 64 + mt * 16 + lrow) * PAD
                                          + ks * 16 + lchunk * 8) * 2;
                ldsm4(ahi[mt], aAhi + off);
                ldsm4(alo[mt], aAlo + off);
            }
            uint32_t bh[2][4];
#pragma unroll
            for (int np = 0; np < 2; np++) {
                uint32_t off = (uint32_t)((wn * 32 + np * 16 + lrow) * PAD
                                          + ks * 16 + lchunk * 8) * 2;
                ldsm4(bh[np], aBhi + off);
            }
#pragma unroll
            for (int mt = 0; mt < 4; mt++)
#pragma unroll
                for (int np = 0; np < 2; np++)
#pragma unroll
                    for (int sub = 0; sub < 2; sub++) {
                        int nt = np * 2 + sub;
                        mma_f16(acc[mt][nt], ahi[mt], bh[np][sub], bh[np][sub + 2]);
                        mma_f16(acc[mt][nt], alo[mt], bh[np][sub], bh[np][sub + 2]);
                    }
        }
    }

    // Epilogue
    const int r0 = lane >> 2;
    const int c0 = (lane & 3) * 2;
#pragma unroll
    for (int mt = 0; mt < 4; mt++) {
#pragma unroll
        for (int nt = 0; nt < 4; nt++) {
            int m = bm + wm * 64 + mt * 16 + r0;
            int n = bn + wn * 32 + nt * 8 + c0;
            float* p0 = &C[(size_t)m * ldc + n];
            float* p1 = &C[(size_t)(m + 8) * ldc + n];
            float* a = acc[mt][nt];
            if (epi == 0) {
                *(float2*)p0 = make_float2(a[0], a[1]);
                *(float2*)p1 = make_float2(a[2], a[3]);
            } else if (epi == 1) {
                float2 o0 = *(float2*)p0, o1 = *(float2*)p1;
                o0.x += a[0]; o0.y += a[1];
                o1.x += a[2]; o1.y += a[3];
                *(float2*)p0 = o0; *(float2*)p1 = o1;
            } else {
                atomicAdd(p0, a[0]); atomicAdd(p0 + 1, a[1]);
                atomicAdd(p1, a[2]); atomicAdd(p1 + 1, a[3]);
            }
        }
    }
}

// ===========================================================================
// CUDA-core SGEMM (xproj): split-K + atomicAdd. blockIdx.z = dir*nsplit + slice.
// ===========================================================================
template<int BM, int BN, int BK, int TM, int TN>
__global__ void sgemm_nt(const float* __restrict__ A, const float* __restrict__ Bm,
                         float* __restrict__ C, int M, int N, int Kt,
                         int lda, int ldb, int ldc, int nsplit,
                         size_t aZ, size_t bZ, size_t cZ)
{
    constexpr int TX = BN / TN;
    constexpr int TY = BM / TM;
    constexpr int THREADS = TX * TY;
    __shared__ float As[BK][BM + 4];
    __shared__ float Bs[BK][BN + 4];

    const int tid = threadIdx.x;
    const int tx = tid % TX;
    const int ty = tid / TX;
    const int bm = blockIdx.y * BM;
    const int bn = blockIdx.x * BN;
    const int dir = blockIdx.z / nsplit;
    const int ksl = blockIdx.z % nsplit;
    A += (size_t)dir * aZ;
    Bm += (size_t)dir * bZ;
    C += (size_t)dir * cZ;
    const int kslice = Kt / nsplit;
    const int kbeg = ksl * kslice;
    const int kend = kbeg + kslice;

    float acc[TM][TN];
#pragma unroll
    for (int m = 0; m < TM; m++)
#pragma unroll
        for (int n = 0; n < TN; n++) acc[m][n] = 0.f;

    for (int k0 = kbeg; k0 < kend; k0 += BK) {
#pragma unroll
        for (int i = 0; i < BM * BK / 4 / THREADS; i++) {
            int idx = tid + i * THREADS;
            int r = idx / (BK / 4);
            int c4 = idx % (BK / 4);
            float4 v = *(const float4*)&A[(size_t)(bm + r) * lda + k0 + c4 * 4];
            As[c4 * 4 + 0][r] = v.x;
            As[c4 * 4 + 1][r] = v.y;
            As[c4 * 4 + 2][r] = v.z;
            As[c4 * 4 + 3][r] = v.w;
        }
#pragma unroll
        for (int i = 0; i < BN * BK / 4 / THREADS; i++) {
            int idx = tid + i * THREADS;
            int r = idx / (BK / 4);
            int c4 = idx % (BK / 4);
            float4 v = *(const float4*)&Bm[(size_t)(bn + r) * ldb + k0 + c4 * 4];
            Bs[c4 * 4 + 0][r] = v.x;
            Bs[c4 * 4 + 1][r] = v.y;
            Bs[c4 * 4 + 2][r] = v.z;
            Bs[c4 * 4 + 3][r] = v.w;
        }
        __syncthreads();

#pragma unroll
        for (int k = 0; k < BK; k++) {
            float ra[TM], rb[TN];
#pragma unroll
            for (int m = 0; m < TM; m++) ra[m] = As[k][ty * TM + m];
#pragma unroll
            for (int n = 0; n < TN; n++) rb[n] = Bs[k][tx * TN + n];
#pragma unroll
            for (int m = 0; m < TM; m++)
#pragma unroll
                for (int n = 0; n < TN; n++)
                    acc[m][n] = fmaf(ra[m], rb[n], acc[m][n]);
        }
        __syncthreads();
    }

#pragma unroll
    for (int m = 0; m < TM; m++) {
        int r = bm + ty * TM + m;
#pragma unroll
        for (int n = 0; n < TN; n++) {
            int c = bn + tx * TN + n;
            atomicAdd(&C[(size_t)r * ldc + c], acc[m][n]);
        }
    }
}

// ===========================================================================
// Causal depthwise conv (K=4) + SiLU, float4 over d. blockIdx.y = dir.
// ===========================================================================
__global__ void conv_silu_kernel(const float* __restrict__ xz,
                                 const float* __restrict__ cw,
                                 const float* __restrict__ cb,
                                 float* __restrict__ xc)
{
    const int dir = blockIdx.y;
    xz += (size_t)dir * XZ_SZ;
    cw += (size_t)dir * DI * KC;
    cb += (size_t)dir * DI;
    xc += (size_t)dir * XC_SZ;
    const int rev = dir;

    int idx = blockIdx.x * blockDim.x + threadIdx.x;   // over B*L*DI/4
    if (idx >= BB * LL * DI / 4) return;
    int d4 = (idx % (DI / 4)) * 4;
    int l  = (idx / (DI / 4)) % LL;
    int b  = idx / ((DI / 4) * LL);

    float4 acc = *(const float4*)(cb + d4);
    float4 w0 = *(const float4*)(cw + (d4 + 0) * KC);
    float4 w1 = *(const float4*)(cw + (d4 + 1) * KC);
    float4 w2 = *(const float4*)(cw + (d4 + 2) * KC);
    float4 w3 = *(const float4*)(cw + (d4 + 3) * KC);
    const float wk0[4] = {w0.x, w0.y, w0.z, w0.w};
    const float wk1[4] = {w1.x, w1.y, w1.z, w1.w};
    const float wk2[4] = {w2.x, w2.y, w2.z, w2.w};
    const float wk3[4] = {w3.x, w3.y, w3.z, w3.w};

#pragma unroll
    for (int k = 0; k < KC; k++) {
        int lp = rev ? (l + (KC - 1) - k) : (l - (KC - 1) + k);
        if (lp >= 0 && lp < LL) {
            float4 v = *(const float4*)(xz + ((size_t)(b * LL + lp)) * 2 * DI + d4);
            acc.x = fmaf(wk0[k], v.x, acc.x);
            acc.y = fmaf(wk1[k], v.y, acc.y);
            acc.z = fmaf(wk2[k], v.z, acc.z);
            acc.w = fmaf(wk3[k], v.w, acc.w);
        }
    }
    acc.x *= 1.f / (1.f + __expf(-acc.x));
    acc.y *= 1.f / (1.f + __expf(-acc.y));
    acc.z *= 1.f / (1.f + __expf(-acc.z));
    acc.w *= 1.f / (1.f + __expf(-acc.w));
    *(float4*)(xc + (size_t)idx * 4) = acc;
}

// ===========================================================================
// Fused dtproj + softplus + selective scan + C-dot + D skip + SiLU(z) gate.
// blockIdx.z = dir. dtw row for each thread's channel preloaded to registers.
// s_raw (dt-proj inputs) overlays the s_c region: temporally disjoint phases.
// ===========================================================================
#define SCH 32
#define SCD 16

__global__ void __launch_bounds__(256) scan_kernel(
                            const float* __restrict__ xc,
                            const float* __restrict__ xz,
                            const float* __restrict__ xdbl,
                            const float* __restrict__ Alog,
                            const float* __restrict__ Dp,
                            const float* __restrict__ dtw,
                            const float* __restrict__ dtb,
                            float* __restrict__ yg)
{
    __shared__ float2 s_dx[SCH][SCD];          // (.x = dt, .y = xc)   4096 B
    __shared__ float  s_z [SCH][SCD];          //                      2048 B
    __shared__ float2 s_bc[SCH][SSN];          // (B, C)               4096 B
    __shared__ float  s_c [SCH][SCD][SSN + 1]; // h*C products        34816 B
    // s_raw overlays s_c (disjoint phases): xdbl[:, 0:32] staging
    float (*s_raw)[RR] = (float (*)[RR])(&s_c[0][0][0]);

    const int tid = threadIdx.x;
    const int cd = tid >> 4;      // chain within block
    const int s  = tid & 15;      // state index
    const int d0 = blockIdx.x * SCD;
    const int b  = blockIdx.y;
    const int dir = blockIdx.z;
    const int rev = dir;
    const int d  = d0 + cd;

    xc   += (size_t)dir * XC_SZ;
    xz   += (size_t)dir * XZ_SZ;
    xdbl += (size_t)dir * XD_SZ;
    yg   += (size_t)dir * YG_SZ;
    Alog += (size_t)dir * DI * SSN;
    Dp   += (size_t)dir * DI;
    dtw  += (size_t)dir * DI * RR;
    dtb  += (size_t)dir * DI;

    const float Aneg = -__expf(Alog[(size_t)d * SSN + s]);

    // Per-thread channel for dt-dot and reduction: dl == tid & 15 everywhere
    const int mydl = tid & 15;
    const float myD = Dp[d0 + mydl];
    float wdt[RR];
#pragma unroll
    for (int k = 0; k < RR; k++) wdt[k] = dtw[(size_t)(d0 + mydl) * RR + k];
    const float mydtb = dtb[d0 + mydl];

    float h = 0.f;

    for (int t0 = 0; t0 < LL; t0 += SCH) {
        // Stage xc / z
#pragma unroll
        for (int it = 0; it < SCH * SCD / 256; it++) {
            int idx = tid + it * 256;
            int j = idx / SCD, dl = idx % SCD;
            int p = rev ? (LL - 1 - (t0 + j)) : (t0 + j);
            size_t row = (size_t)(b * LL + p);
            s_dx[j][dl].y = xc[row * DI + d0 + dl];
            s_z [j][dl]   = xz[row * 2 * DI + DI + d0 + dl];
        }
        // Stage xdbl full 64 cols: 0..31 -> s_raw (overlay), 32..47 -> B, 48..63 -> C
#pragma unroll
        for (int it = 0; it < SCH * 64 / 256; it++) {
            int idx = tid + it * 256;
            int j = idx / 64, c = idx % 64;
            int p = rev ? (LL - 1 - (t0 + j)) : (t0 + j);
            float v = xdbl[(size_t)(b * LL + p) * 64 + c];
            if (c < RR)            s_raw[j][c] = v;
            else if (c < RR + SSN) s_bc[j][c - RR].x = v;
            else                   s_bc[j][c - RR - SSN].y = v;
        }
        __syncthreads();

        // dt = softplus(xdbl[:, :32] @ dtw[d] + dtb[d]) — 2 (j, dl) pairs/thread
#pragma unroll
        for (int it = 0; it < SCH * SCD / 256; it++) {
            int idx = tid + it * 256;
            int j = idx / SCD;                 // dl == mydl by construction
            float u = mydtb;
#pragma unroll
            for (int k = 0; k < RR; k++) u = fmaf(s_raw[j][k], wdt[k], u);
            float sp = (u > 0.f) ? (u + log1pf(__expf(-u))) : log1pf(__expf(u));
            s_dx[j][mydl].x = sp;
        }
        __syncthreads();   // s_raw fully consumed; s_c region may now be written

        // Serial scan: only the h-FFMA is serial
#pragma unroll 8
        for (int j = 0; j < SCH; j++) {
            float2 dx = s_dx[j][cd];
            float2 bc = s_bc[j][s];
            float dA = __expf(dx.x * Aneg);
            h = fmaf(dA, h, dx.x * dx.y * bc.x);
            s_c[j][cd][s] = h * bc.y;
        }
        __syncthreads();

        // Parallel state-reduction + D skip + SiLU(z) gate + store (dl == mydl)
#pragma unroll
        for (int it = 0; it < SCH * SCD / 256; it++) {
            int idx = tid + it * 256;
            int j = idx / SCD, dl = idx % SCD;
            float sum = 0.f;
#pragma unroll
            for (int ss = 0; ss < SSN; ss++) sum += s_c[j][dl][ss];
            float y = fmaf(s_dx[j][dl].y, myD, sum);
            float zv = s_z[j][dl];
            y *= zv / (1.f + __expf(-zv));
            int p = rev ? (LL - 1 - (t0 + j)) : (t0 + j);
            yg[(size_t)(b * LL + p) * DI + d0 + dl] = y;
        }
        __syncthreads();
    }
}

// ===========================================================================
// LayerNorm + copy + zero
// ===========================================================================
__global__ void layernorm_kernel(const float* __restrict__ acc,
                                 const float* __restrict__ g,
                                 const float* __restrict__ bta,
                                 float* __restrict__ out)
{
    __shared__ float red[256];
    int row = blockIdx.x;
    int t = threadIdx.x;
    const float* rp = acc + (size_t)row * NN;

    float v0 = rp[t];
    float v1 = rp[t + 256];

    red[t] = v0 + v1;
    __syncthreads();
    for (int o = 128; o > 0; o >>= 1) {
        if (t < o) red[t] += red[t + o];
        __syncthreads();
    }
    float mu = red[0] * (1.f / NN);
    __syncthreads();

    float c0 = v0 - mu, c1 = v1 - mu;
    red[t] = c0 * c0 + c1 * c1;
    __syncthreads();
    for (int o = 128; o > 0; o >>= 1) {
        if (t < o) red[t] += red[t + o];
        __syncthreads();
    }
    float inv = rsqrtf(red[0] * (1.f / NN) + EPS);

    float* op = out + (size_t)row * NN;
    op[t]       = c0 * inv * g[t]       + bta[t];
    op[t + 256] = c1 * inv * g[t + 256] + bta[t + 256];
}

__global__ void copy_kernel(float* __restrict__ dst, const float* __restrict__ src, int n4)
{
    int i = blockIdx.x * blockDim.x + threadIdx.x;
    if (i < n4) ((float4*)dst)[i] = ((const float4*)src)[i];
}

__global__ void zero_kernel(float* __restrict__ dst, int n4)
{
    int i = blockIdx.x * blockDim.x + threadIdx.x;
    if (i < n4) ((float4*)dst)[i] = make_float4(0.f, 0.f, 0.f, 0.f);
}

// ===========================================================================
extern "C" void kernel_launch(void* const* d_in, const int* in_sizes, int n_in,
                              void* d_out, int out_size)
{
    const float* x    = (const float*)d_in[0];
    const float* inw  = (const float*)d_in[1];
    const float* cw   = (const float*)d_in[2];
    const float* cb   = (const float*)d_in[3];
    const float* xw   = (const float*)d_in[4];
    const float* dtw  = (const float*)d_in[5];
    const float* dtb  = (const float*)d_in[6];
    const float* Alog = (const float*)d_in[7];
    const float* Dp   = (const float*)d_in[8];
    const float* ow   = (const float*)d_in[9];
    const float* lng  = (const float*)d_in[10];
    const float* lnb  = (const float*)d_in[11];

    float *xz, *xc, *xdbl, *yg, *acc, *cur;
    cudaGetSymbolAddress((void**)&xz,   g_xz);
    cudaGetSymbolAddress((void**)&xc,   g_xc);
    cudaGetSymbolAddress((void**)&xdbl, g_xdbl);
    cudaGetSymbolAddress((void**)&yg,   g_yg);
    cudaGetSymbolAddress((void**)&acc,  g_acc);
    cudaGetSymbolAddress((void**)&cur,  g_cur);

    static int smem_set = 0;
    if (!smem_set) {
        cudaFuncSetAttribute(hgemm_nt, cudaFuncAttributeMaxDynamicSharedMemorySize, HG_SMEM);
        smem_set = 1;
    }

    const float* layer_in = x;

    for (int l = 0; l < NLAYER; l++) {
        const size_t i0 = 2 * l;  // weight index of fwd direction

        // acc = residual
        copy_kernel<<<(MROWS * NN / 4 + 255) / 256, 256>>>(acc, layer_in, MROWS * NN / 4);

        // in_proj, both dirs: xz[dir] = layer_in @ inw[i0+dir]^T
        hgemm_nt<<<dim3(2 * DI / 128, MROWS / 128, 2), 256, HG_SMEM>>>(
            layer_in, inw + i0 * 2 * DI * NN, xz,
            NN, NN, NN, 2 * DI, /*epi*/0, /*nsplit*/1,
            0, (size_t)2 * DI * NN, XZ_SZ);

        // conv + SiLU, both dirs
        conv_silu_kernel<<<dim3((BB * LL * DI / 4 + 255) / 256, 2), 256>>>(
            xz, cw + i0 * DI * KC, cb + i0 * DI, xc);

        // xproj, both dirs, split-K=8 + atomics: xdbl[dir] = xc[dir] @ xw^T
        zero_kernel<<<(2 * (int)XD_SZ / 4 + 255) / 256, 256>>>(xdbl, 2 * (int)XD_SZ / 4);
        sgemm_nt<64, 64, 16, 4, 4><<<dim3(1, MROWS / 64, 16), 256>>>(
            xc, xw + i0 * 64 * DI, xdbl,
            MROWS, 64, DI, DI, DI, 64, /*nsplit*/8,
            XC_SZ, (size_t)64 * DI, XD_SZ);

        // fused dtproj + scan + gate, both dirs
        scan_kernel<<<dim3(DI / SCD, BB, 2), 256>>>(
            xc, xz, xdbl,
            Alog + i0 * DI * SSN, Dp + i0 * DI,
            dtw + i0 * DI * RR, dtb + i0 * DI, yg);

        // out_proj, both dirs x split-K=2, atomic into residual
        hgemm_nt<<<dim3(NN / 128, MROWS / 128, 4), 256, HG_SMEM>>>(
            yg, ow + i0 * NN * DI, acc,
            DI, DI, DI, NN, /*epi*/2, /*nsplit*/2,
            YG_SZ, (size_t)NN * DI, 0);

        float* lnout = (l == NLAYER - 1) ? (float*)d_out : cur;
        layernorm_kernel<<<MROWS, 256>>>(acc, lng + (size_t)l * NN, lnb + (size_t)l * NN, lnout);
        layer_in = cur;
    }
}

// round 12
// speedup vs baseline: 2.8214x; 1.1330x over previous
#include <cuda_runtime.h>
#include <cuda_fp16.h>
#include <math.h>
#include <stdint.h>

// Problem constants
#define BB 2
#define LL 1024
#define NN 512
#define NLAYER 2
#define DI 1024
#define SSN 16
#define KC 4
#define RR 32
#define EPS 1e-5f
#define MROWS (BB*LL)   // 2048

// Per-direction buffer sizes (elements)
#define XZ_SZ ((size_t)MROWS * 2 * DI)
#define XC_SZ ((size_t)MROWS * DI)
#define XD_SZ ((size_t)MROWS * 64)
#define YG_SZ ((size_t)MROWS * DI)

// Scratch buffers (static device globals; no runtime allocation)
__device__ __align__(256) float g_xz  [2 * XZ_SZ];
__device__ __align__(256) float g_xc  [2 * XC_SZ];
__device__ __align__(256) float g_xdbl[2 * XD_SZ];
__device__ __align__(256) float g_yg  [2 * YG_SZ];
__device__ __align__(256) float g_acc [(size_t)MROWS * NN];
__device__ __align__(256) float g_cur [(size_t)MROWS * NN];

// ===========================================================================
// Helpers
// ===========================================================================
static __device__ __forceinline__ uint32_t smem_u32(const void* p) {
    uint32_t a;
    asm("{ .reg .u64 t; cvta.to.shared.u64 t, %1; cvt.u32.u64 %0, t; }" : "=r"(a) : "l"(p));
    return a;
}

static __device__ __forceinline__ void ldsm4(uint32_t* r, uint32_t addr) {
    asm volatile("ldmatrix.sync.aligned.m8n8.x4.shared.b16 {%0,%1,%2,%3}, [%4];"
        : "=r"(r[0]), "=r"(r[1]), "=r"(r[2]), "=r"(r[3]) : "r"(addr));
}

static __device__ __forceinline__ void mma_f16(float* c, const uint32_t* a,
                                               uint32_t b0, uint32_t b1) {
    asm volatile(
        "mma.sync.aligned.m16n8k16.row.col.f32.f16.f16.f32 "
        "{%0,%1,%2,%3}, {%4,%5,%6,%7}, {%8,%9}, {%0,%1,%2,%3};"
        : "+f"(c[0]), "+f"(c[1]), "+f"(c[2]), "+f"(c[3])
        : "r"(a[0]), "r"(a[1]), "r"(a[2]), "r"(a[3]), "r"(b0), "r"(b1));
}

#define CP_ASYNC16(smem, gptr) \
    asm volatile("cp.async.cg.shared.global [%0], [%1], 16;" :: "r"(smem), "l"(gptr) : "memory")
#define CP_COMMIT() asm volatile("cp.async.commit_group;" ::: "memory")

// ===========================================================================
// fp16 NT GEMM, cp.async double-buffered: C (+)= A @ B^T, fp32 I/O.
// Single fp16 for A and B, 1 MMA/k-step. Block 128x128, 8 warps of 64x32.
// blockIdx.z = dir*nsplit + kslice; per-dir pointer strides aZ/bZ/cZ.
// epi: 0 = store, 1 = add, 2 = atomicAdd
// ===========================================================================
#define PAD 40
#define HG_STAGE 16384                       // 128*32*4 bytes per fp32 tile
#define HG_TILE  (128*PAD)                   // fp16 elems per tile
#define HG_SMEM  (4*HG_STAGE + 2*HG_TILE*2)  // 65536 + 20480 = 86016 bytes

__global__ void __launch_bounds__(256, 2) hgemm_nt(
    const float* __restrict__ A, const float* __restrict__ Bw, float* __restrict__ C,
    int K, int lda, int ldb, int ldc, int epi, int nsplit,
    size_t aZ, size_t bZ, size_t cZ)
{
    extern __shared__ char dsm[];
    float* stA[2] = {(float*)dsm,                  (float*)(dsm + 2*HG_STAGE)};
    float* stB[2] = {(float*)(dsm + HG_STAGE),     (float*)(dsm + 3*HG_STAGE)};
    __half* sAhi = (__half*)(dsm + 4*HG_STAGE);
    __half* sBhi = sAhi + HG_TILE;

    const int tid = threadIdx.x;
    const int wid = tid >> 5, lane = tid & 31;
    const int wm = wid >> 2, wn = wid & 3;
    const int bm = blockIdx.y * 128, bn = blockIdx.x * 128;
    const int dir = blockIdx.z / nsplit;
    const int ksl = blockIdx.z % nsplit;
    A  += (size_t)dir * aZ;
    Bw += (size_t)dir * bZ;
    C  += (size_t)dir * cZ;
    const int kslice = K / nsplit;
    const int kbeg = ksl * kslice;
    const int nch = kslice / 32;

    const uint32_t uA[2] = {smem_u32(stA[0]), smem_u32(stA[1])};
    const uint32_t uB[2] = {smem_u32(stB[0]), smem_u32(stB[1])};
    const uint32_t aAhi = smem_u32(sAhi);
    const uint32_t aBhi = smem_u32(sBhi);

    const int lrow = lane & 15;
    const int lchunk = lane >> 4;

    float acc[4][4][4];
#pragma unroll
    for (int i = 0; i < 4; i++)
#pragma unroll
        for (int j = 0; j < 4; j++)
#pragma unroll
            for (int q = 0; q < 4; q++) acc[i][j][q] = 0.f;

    auto issue_chunk = [&](int kc, int buf) {
        const float* Ab = A + (size_t)bm * lda + kbeg + kc * 32;
        const float* Bb = Bw + (size_t)bn * ldb + kbeg + kc * 32;
#pragma unroll
        for (int i = 0; i < 4; i++) {
            int idx = tid + i * 256;
            int r = idx >> 3, c = (idx & 7) * 4;
            uint32_t off = (uint32_t)(r * 32 + c) * 4;
            CP_ASYNC16(uA[buf] + off, Ab + (size_t)r * lda + c);
            CP_ASYNC16(uB[buf] + off, Bb + (size_t)r * ldb + c);
        }
        CP_COMMIT();
    };

    issue_chunk(0, 0);

    for (int kc = 0; kc < nch; kc++) {
        if (kc + 1 < nch) {
            issue_chunk(kc + 1, (kc + 1) & 1);
            asm volatile("cp.async.wait_group 1;" ::: "memory");
        } else {
            asm volatile("cp.async.wait_group 0;" ::: "memory");
        }
        __syncthreads();   // stage[kc&1] visible; prev MMA done (tiles reusable)

        // Convert fp32 stage -> fp16 tiles
        const float* sA = stA[kc & 1];
        const float* sB = stB[kc & 1];
#pragma unroll
        for (int i = 0; i < 4; i++) {
            int idx = tid + i * 256;
            int r = idx >> 3, c = (idx & 7) * 4;
            int soff = r * 32 + c;
            int toff = r * PAD + c;
            float4 va = *(const float4*)(sA + soff);
            *(__half2*)(sAhi + toff)     = __floats2half2_rn(va.x, va.y);
            *(__half2*)(sAhi + toff + 2) = __floats2half2_rn(va.z, va.w);
            float4 vb = *(const float4*)(sB + soff);
            *(__half2*)(sBhi + toff)     = __floats2half2_rn(vb.x, vb.y);
            *(__half2*)(sBhi + toff + 2) = __floats2half2_rn(vb.z, vb.w);
        }
        __syncthreads();

#pragma unroll
        for (int ks = 0; ks < 2; ks++) {
            uint32_t ahi[4][4];
#pragma unroll
            for (int mt = 0; mt < 4; mt++) {
                uint32_t off = (uint32_t)((wm * 64 + mt * 16 + lrow) * PAD
                                          + ks * 16 + lchunk * 8) * 2;
                ldsm4(ahi[mt], aAhi + off);
            }
            uint32_t bh[2][4];
#pragma unroll
            for (int np = 0; np < 2; np++) {
                uint32_t off = (uint32_t)((wn * 32 + np * 16 + lrow) * PAD
                                          + ks * 16 + lchunk * 8) * 2;
                ldsm4(bh[np], aBhi + off);
            }
#pragma unroll
            for (int mt = 0; mt < 4; mt++)
#pragma unroll
                for (int np = 0; np < 2; np++)
#pragma unroll
                    for (int sub = 0; sub < 2; sub++) {
                        int nt = np * 2 + sub;
                        mma_f16(acc[mt][nt], ahi[mt], bh[np][sub], bh[np][sub + 2]);
                    }
        }
    }

    // Epilogue
    const int r0 = lane >> 2;
    const int c0 = (lane & 3) * 2;
#pragma unroll
    for (int mt = 0; mt < 4; mt++) {
#pragma unroll
        for (int nt = 0; nt < 4; nt++) {
            int m = bm + wm * 64 + mt * 16 + r0;
            int n = bn + wn * 32 + nt * 8 + c0;
            float* p0 = &C[(size_t)m * ldc + n];
            float* p1 = &C[(size_t)(m + 8) * ldc + n];
            float* a = acc[mt][nt];
            if (epi == 0) {
                *(float2*)p0 = make_float2(a[0], a[1]);
                *(float2*)p1 = make_float2(a[2], a[3]);
            } else if (epi == 1) {
                float2 o0 = *(float2*)p0, o1 = *(float2*)p1;
                o0.x += a[0]; o0.y += a[1];
                o1.x += a[2]; o1.y += a[3];
                *(float2*)p0 = o0; *(float2*)p1 = o1;
            } else {
                atomicAdd(p0, a[0]); atomicAdd(p0 + 1, a[1]);
                atomicAdd(p1, a[2]); atomicAdd(p1 + 1, a[3]);
            }
        }
    }
}

// ===========================================================================
// CUDA-core SGEMM (xproj): split-K + atomicAdd. blockIdx.z = dir*nsplit + slice.
// ===========================================================================
template<int BM, int BN, int BK, int TM, int TN>
__global__ void sgemm_nt(const float* __restrict__ A, const float* __restrict__ Bm,
                         float* __restrict__ C, int M, int N, int Kt,
                         int lda, int ldb, int ldc, int nsplit,
                         size_t aZ, size_t bZ, size_t cZ)
{
    constexpr int TX = BN / TN;
    constexpr int TY = BM / TM;
    constexpr int THREADS = TX * TY;
    __shared__ float As[BK][BM + 4];
    __shared__ float Bs[BK][BN + 4];

    const int tid = threadIdx.x;
    const int tx = tid % TX;
    const int ty = tid / TX;
    const int bm = blockIdx.y * BM;
    const int bn = blockIdx.x * BN;
    const int dir = blockIdx.z / nsplit;
    const int ksl = blockIdx.z % nsplit;
    A += (size_t)dir * aZ;
    Bm += (size_t)dir * bZ;
    C += (size_t)dir * cZ;
    const int kslice = Kt / nsplit;
    const int kbeg = ksl * kslice;
    const int kend = kbeg + kslice;

    float acc[TM][TN];
#pragma unroll
    for (int m = 0; m < TM; m++)
#pragma unroll
        for (int n = 0; n < TN; n++) acc[m][n] = 0.f;

    for (int k0 = kbeg; k0 < kend; k0 += BK) {
#pragma unroll
        for (int i = 0; i < BM * BK / 4 / THREADS; i++) {
            int idx = tid + i * THREADS;
            int r = idx / (BK / 4);
            int c4 = idx % (BK / 4);
            float4 v = *(const float4*)&A[(size_t)(bm + r) * lda + k0 + c4 * 4];
            As[c4 * 4 + 0][r] = v.x;
            As[c4 * 4 + 1][r] = v.y;
            As[c4 * 4 + 2][r] = v.z;
            As[c4 * 4 + 3][r] = v.w;
        }
#pragma unroll
        for (int i = 0; i < BN * BK / 4 / THREADS; i++) {
            int idx = tid + i * THREADS;
            int r = idx / (BK / 4);
            int c4 = idx % (BK / 4);
            float4 v = *(const float4*)&Bm[(size_t)(bn + r) * ldb + k0 + c4 * 4];
            Bs[c4 * 4 + 0][r] = v.x;
            Bs[c4 * 4 + 1][r] = v.y;
            Bs[c4 * 4 + 2][r] = v.z;
            Bs[c4 * 4 + 3][r] = v.w;
        }
        __syncthreads();

#pragma unroll
        for (int k = 0; k < BK; k++) {
            float ra[TM], rb[TN];
#pragma unroll
            for (int m = 0; m < TM; m++) ra[m] = As[k][ty * TM + m];
#pragma unroll
            for (int n = 0; n < TN; n++) rb[n] = Bs[k][tx * TN + n];
#pragma unroll
            for (int m = 0; m < TM; m++)
#pragma unroll
                for (int n = 0; n < TN; n++)
                    acc[m][n] = fmaf(ra[m], rb[n], acc[m][n]);
        }
        __syncthreads();
    }

#pragma unroll
    for (int m = 0; m < TM; m++) {
        int r = bm + ty * TM + m;
#pragma unroll
        for (int n = 0; n < TN; n++) {
            int c = bn + tx * TN + n;
            atomicAdd(&C[(size_t)r * ldc + c], acc[m][n]);
        }
    }
}

// ===========================================================================
// Causal depthwise conv (K=4) + SiLU, float4 over d. blockIdx.y = dir.
// ===========================================================================
__global__ void conv_silu_kernel(const float* __restrict__ xz,
                                 const float* __restrict__ cw,
                                 const float* __restrict__ cb,
                                 float* __restrict__ xc)
{
    const int dir = blockIdx.y;
    xz += (size_t)dir * XZ_SZ;
    cw += (size_t)dir * DI * KC;
    cb += (size_t)dir * DI;
    xc += (size_t)dir * XC_SZ;
    const int rev = dir;

    int idx = blockIdx.x * blockDim.x + threadIdx.x;   // over B*L*DI/4
    if (idx >= BB * LL * DI / 4) return;
    int d4 = (idx % (DI / 4)) * 4;
    int l  = (idx / (DI / 4)) % LL;
    int b  = idx / ((DI / 4) * LL);

    float4 acc = *(const float4*)(cb + d4);
    float4 w0 = *(const float4*)(cw + (d4 + 0) * KC);
    float4 w1 = *(const float4*)(cw + (d4 + 1) * KC);
    float4 w2 = *(const float4*)(cw + (d4 + 2) * KC);
    float4 w3 = *(const float4*)(cw + (d4 + 3) * KC);
    const float wk0[4] = {w0.x, w0.y, w0.z, w0.w};
    const float wk1[4] = {w1.x, w1.y, w1.z, w1.w};
    const float wk2[4] = {w2.x, w2.y, w2.z, w2.w};
    const float wk3[4] = {w3.x, w3.y, w3.z, w3.w};

#pragma unroll
    for (int k = 0; k < KC; k++) {
        int lp = rev ? (l + (KC - 1) - k) : (l - (KC - 1) + k);
        if (lp >= 0 && lp < LL) {
            float4 v = *(const float4*)(xz + ((size_t)(b * LL + lp)) * 2 * DI + d4);
            acc.x = fmaf(wk0[k], v.x, acc.x);
            acc.y = fmaf(wk1[k], v.y, acc.y);
            acc.z = fmaf(wk2[k], v.z, acc.z);
            acc.w = fmaf(wk3[k], v.w, acc.w);
        }
    }
    acc.x *= 1.f / (1.f + __expf(-acc.x));
    acc.y *= 1.f / (1.f + __expf(-acc.y));
    acc.z *= 1.f / (1.f + __expf(-acc.z));
    acc.w *= 1.f / (1.f + __expf(-acc.w));
    *(float4*)(xc + (size_t)idx * 4) = acc;
}

// ===========================================================================
// Fused dtproj + softplus + selective scan + C-dot + D skip + SiLU(z) gate.
// blockIdx.z = dir. dtw row for each thread's channel preloaded to registers.
// s_raw (dt-proj inputs) overlays the s_c region: temporally disjoint phases.
// ===========================================================================
#define SCH 32
#define SCD 16

__global__ void __launch_bounds__(256) scan_kernel(
                            const float* __restrict__ xc,
                            const float* __restrict__ xz,
                            const float* __restrict__ xdbl,
                            const float* __restrict__ Alog,
                            const float* __restrict__ Dp,
                            const float* __restrict__ dtw,
                            const float* __restrict__ dtb,
                            float* __restrict__ yg)
{
    __shared__ float2 s_dx[SCH][SCD];          // (.x = dt, .y = xc)   4096 B
    __shared__ float  s_z [SCH][SCD];          //                      2048 B
    __shared__ float2 s_bc[SCH][SSN];          // (B, C)               4096 B
    __shared__ float  s_c [SCH][SCD][SSN + 1]; // h*C products        34816 B
    // s_raw overlays s_c (disjoint phases): xdbl[:, 0:32] staging
    float (*s_raw)[RR] = (float (*)[RR])(&s_c[0][0][0]);

    const int tid = threadIdx.x;
    const int cd = tid >> 4;      // chain within block
    const int s  = tid & 15;      // state index
    const int d0 = blockIdx.x * SCD;
    const int b  = blockIdx.y;
    const int dir = blockIdx.z;
    const int rev = dir;
    const int d  = d0 + cd;

    xc   += (size_t)dir * XC_SZ;
    xz   += (size_t)dir * XZ_SZ;
    xdbl += (size_t)dir * XD_SZ;
    yg   += (size_t)dir * YG_SZ;
    Alog += (size_t)dir * DI * SSN;
    Dp   += (size_t)dir * DI;
    dtw  += (size_t)dir * DI * RR;
    dtb  += (size_t)dir * DI;

    const float Aneg = -__expf(Alog[(size_t)d * SSN + s]);

    // Per-thread channel for dt-dot and reduction: dl == tid & 15 everywhere
    const int mydl = tid & 15;
    const float myD = Dp[d0 + mydl];
    float wdt[RR];
#pragma unroll
    for (int k = 0; k < RR; k++) wdt[k] = dtw[(size_t)(d0 + mydl) * RR + k];
    const float mydtb = dtb[d0 + mydl];

    float h = 0.f;

    for (int t0 = 0; t0 < LL; t0 += SCH) {
        // Stage xc / z
#pragma unroll
        for (int it = 0; it < SCH * SCD / 256; it++) {
            int idx = tid + it * 256;
            int j = idx / SCD, dl = idx % SCD;
            int p = rev ? (LL - 1 - (t0 + j)) : (t0 + j);
            size_t row = (size_t)(b * LL + p);
            s_dx[j][dl].y = xc[row * DI + d0 + dl];
            s_z [j][dl]   = xz[row * 2 * DI + DI + d0 + dl];
        }
        // Stage xdbl full 64 cols: 0..31 -> s_raw (overlay), 32..47 -> B, 48..63 -> C
#pragma unroll
        for (int it = 0; it < SCH * 64 / 256; it++) {
            int idx = tid + it * 256;
            int j = idx / 64, c = idx % 64;
            int p = rev ? (LL - 1 - (t0 + j)) : (t0 + j);
            float v = xdbl[(size_t)(b * LL + p) * 64 + c];
            if (c < RR)            s_raw[j][c] = v;
            else if (c < RR + SSN) s_bc[j][c - RR].x = v;
            else                   s_bc[j][c - RR - SSN].y = v;
        }
        __syncthreads();

        // dt = softplus(xdbl[:, :32] @ dtw[d] + dtb[d]) — 2 (j, dl) pairs/thread
#pragma unroll
        for (int it = 0; it < SCH * SCD / 256; it++) {
            int idx = tid + it * 256;
            int j = idx / SCD;                 // dl == mydl by construction
            float u = mydtb;
#pragma unroll
            for (int k = 0; k < RR; k++) u = fmaf(s_raw[j][k], wdt[k], u);
            float sp = (u > 0.f) ? (u + log1pf(__expf(-u))) : log1pf(__expf(u));
            s_dx[j][mydl].x = sp;
        }
        __syncthreads();   // s_raw fully consumed; s_c region may now be written

        // Serial scan: only the h-FFMA is serial
#pragma unroll 8
        for (int j = 0; j < SCH; j++) {
            float2 dx = s_dx[j][cd];
            float2 bc = s_bc[j][s];
            float dA = __expf(dx.x * Aneg);
            h = fmaf(dA, h, dx.x * dx.y * bc.x);
            s_c[j][cd][s] = h * bc.y;
        }
        __syncthreads();

        // Parallel state-reduction + D skip + SiLU(z) gate + store (dl == mydl)
#pragma unroll
        for (int it = 0; it < SCH * SCD / 256; it++) {
            int idx = tid + it * 256;
            int j = idx / SCD, dl = idx % SCD;
            float sum = 0.f;
#pragma unroll
            for (int ss = 0; ss < SSN; ss++) sum += s_c[j][dl][ss];
            float y = fmaf(s_dx[j][dl].y, myD, sum);
            float zv = s_z[j][dl];
            y *= zv / (1.f + __expf(-zv));
            int p = rev ? (LL - 1 - (t0 + j)) : (t0 + j);
            yg[(size_t)(b * LL + p) * DI + d0 + dl] = y;
        }
        __syncthreads();
    }
}

// ===========================================================================
// LayerNorm + copy + zero
// ===========================================================================
__global__ void layernorm_kernel(const float* __restrict__ acc,
                                 const float* __restrict__ g,
                                 const float* __restrict__ bta,
                                 float* __restrict__ out)
{
    __shared__ float red[256];
    int row = blockIdx.x;
    int t = threadIdx.x;
    const float* rp = acc + (size_t)row * NN;

    float v0 = rp[t];
    float v1 = rp[t + 256];

    red[t] = v0 + v1;
    __syncthreads();
    for (int o = 128; o > 0; o >>= 1) {
        if (t < o) red[t] += red[t + o];
        __syncthreads();
    }
    float mu = red[0] * (1.f / NN);
    __syncthreads();

    float c0 = v0 - mu, c1 = v1 - mu;
    red[t] = c0 * c0 + c1 * c1;
    __syncthreads();
    for (int o = 128; o > 0; o >>= 1) {
        if (t < o) red[t] += red[t + o];
        __syncthreads();
    }
    float inv = rsqrtf(red[0] * (1.f / NN) + EPS);

    float* op = out + (size_t)row * NN;
    op[t]       = c0 * inv * g[t]       + bta[t];
    op[t + 256] = c1 * inv * g[t + 256] + bta[t + 256];
}

__global__ void copy_kernel(float* __restrict__ dst, const float* __restrict__ src, int n4)
{
    int i = blockIdx.x * blockDim.x + threadIdx.x;
    if (i < n4) ((float4*)dst)[i] = ((const float4*)src)[i];
}

__global__ void zero_kernel(float* __restrict__ dst, int n4)
{
    int i = blockIdx.x * blockDim.x + threadIdx.x;
    if (i < n4) ((float4*)dst)[i] = make_float4(0.f, 0.f, 0.f, 0.f);
}

// ===========================================================================
extern "C" void kernel_launch(void* const* d_in, const int* in_sizes, int n_in,
                              void* d_out, int out_size)
{
    const float* x    = (const float*)d_in[0];
    const float* inw  = (const float*)d_in[1];
    const float* cw   = (const float*)d_in[2];
    const float* cb   = (const float*)d_in[3];
    const float* xw   = (const float*)d_in[4];
    const float* dtw  = (const float*)d_in[5];
    const float* dtb  = (const float*)d_in[6];
    const float* Alog = (const float*)d_in[7];
    const float* Dp   = (const float*)d_in[8];
    const float* ow   = (const float*)d_in[9];
    const float* lng  = (const float*)d_in[10];
    const float* lnb  = (const float*)d_in[11];

    float *xz, *xc, *xdbl, *yg, *acc, *cur;
    cudaGetSymbolAddress((void**)&xz,   g_xz);
    cudaGetSymbolAddress((void**)&xc,   g_xc);
    cudaGetSymbolAddress((void**)&xdbl, g_xdbl);
    cudaGetSymbolAddress((void**)&yg,   g_yg);
    cudaGetSymbolAddress((void**)&acc,  g_acc);
    cudaGetSymbolAddress((void**)&cur,  g_cur);

    static int smem_set = 0;
    if (!smem_set) {
        cudaFuncSetAttribute(hgemm_nt, cudaFuncAttributeMaxDynamicSharedMemorySize, HG_SMEM);
        smem_set = 1;
    }

    const float* layer_in = x;

    for (int l = 0; l < NLAYER; l++) {
        const size_t i0 = 2 * l;  // weight index of fwd direction

        // acc = residual
        copy_kernel<<<(MROWS * NN / 4 + 255) / 256, 256>>>(acc, layer_in, MROWS * NN / 4);

        // in_proj, both dirs: xz[dir] = layer_in @ inw[i0+dir]^T
        hgemm_nt<<<dim3(2 * DI / 128, MROWS / 128, 2), 256, HG_SMEM>>>(
            layer_in, inw + i0 * 2 * DI * NN, xz,
            NN, NN, NN, 2 * DI, /*epi*/0, /*nsplit*/1,
            0, (size_t)2 * DI * NN, XZ_SZ);

        // conv + SiLU, both dirs
        conv_silu_kernel<<<dim3((BB * LL * DI / 4 + 255) / 256, 2), 256>>>(
            xz, cw + i0 * DI * KC, cb + i0 * DI, xc);

        // xproj, both dirs, split-K=8 + atomics: xdbl[dir] = xc[dir] @ xw^T
        zero_kernel<<<(2 * (int)XD_SZ / 4 + 255) / 256, 256>>>(xdbl, 2 * (int)XD_SZ / 4);
        sgemm_nt<64, 64, 16, 4, 4><<<dim3(1, MROWS / 64, 16), 256>>>(
            xc, xw + i0 * 64 * DI, xdbl,
            MROWS, 64, DI, DI, DI, 64, /*nsplit*/8,
            XC_SZ, (size_t)64 * DI, XD_SZ);

        // fused dtproj + scan + gate, both dirs
        scan_kernel<<<dim3(DI / SCD, BB, 2), 256>>>(
            xc, xz, xdbl,
            Alog + i0 * DI * SSN, Dp + i0 * DI,
            dtw + i0 * DI * RR, dtb + i0 * DI, yg);

        // out_proj, both dirs x split-K=2, atomic into residual
        hgemm_nt<<<dim3(NN / 128, MROWS / 128, 4), 256, HG_SMEM>>>(
            yg, ow + i0 * NN * DI, acc,
            DI, DI, DI, NN, /*epi*/2, /*nsplit*/2,
            YG_SZ, (size_t)NN * DI, 0);

        float* lnout = (l == NLAYER - 1) ? (float*)d_out : cur;
        layernorm_kernel<<<MROWS, 256>>>(acc, lng + (size_t)l * NN, lnb + (size_t)l * NN, lnout);
        layer_in = cur;
    }
}